// round 13
// baseline (speedup 1.0000x reference)
#include <cuda_runtime.h>
#include <cuda_bf16.h>
#include <cstddef>
#include <cstdint>

#define HW     2304
#define CH     768
#define NH     12
#define HD     64
#define SH     48
#define QSCALE 0.125f
#define OUT_ELEMS (HW * CH)
#define NTILES 36            // 2304 / 64 n-tiles per row
#define KSPLIT 4             // attnv split-K segments

// stage layout (49152 B per stage): A_HI 0, A_LO 16384, B_HI 32768, B_LO 40960
#define A_HI  0
#define A_LO  16384
#define B_HI  32768
#define B_LO  40960
#define STAGE 49152
#define ROWC  49152          // scores LUT / spare area after stage 0
#define SMEM_1S (49152 + 512 + 1024)
#define SMEM_2S (2 * 49152 + 1024)
#define SMEM_AV (2 * 49152 + 512 + 1024)   // attnv: 2 stages + sC

// -------- scratch --------
__device__ uint4  g_Xs [216][2048];      // X A-tiles   (18 mt x 12 kt) 32KB each
__device__ uint4  g_Qs [216][2048];      // Q A-tiles   (12 h  x 18 mt)
__device__ uint4  g_Ks [432][1024];      // K B-tiles   (12 h  x 36 nt) 16KB each
__device__ uint4  g_Vs [432][1024];      // V B-tiles   (12 h  x 36 kt)
__device__ uint4  g_Ws [4][144][1024];   // weight B-tiles (12 nt x 12 kt)
__device__ uint4  g_OHs[216][2048];      // OH A-tiles  (18 mt x 12 kt)

__device__ float  g_Q[HW * CH];              // fp32 Q (relpos input)
__device__ float  g_pOH[KSPLIT][HW * CH];    // attnv split-K partials
__device__ float  g_relh[NH * HW * SH];
__device__ float  g_relw[NH * HW * SH];
__device__ float2 g_part[NH * HW * NTILES];  // per (row, ntile): {max, expsum}
__device__ float  g_rowC[NH * HW];           // M + ln(S) per row

// ---------------- helpers ----------------
__device__ __forceinline__ uint32_t smem_u32(const void* p) {
    uint32_t a;
    asm("{ .reg .u64 t; cvta.to.shared.u64 t, %1; cvt.u32.u64 %0, t; }" : "=r"(a) : "l"(p));
    return a;
}

__device__ __forceinline__ void cpa16(uint32_t saddr, const void* g) {
    asm volatile("cp.async.cg.shared.global [%0], [%1], 16;"
        :: "r"(saddr), "l"(g) : "memory");
}
#define CP_COMMIT() asm volatile("cp.async.commit_group;" ::: "memory")
#define CP_WAIT0()  asm volatile("cp.async.wait_group 0;" ::: "memory")
#define CP_WAIT1()  asm volatile("cp.async.wait_group 1;" ::: "memory")

__device__ __forceinline__ void ldsm4(uint32_t* r, uint32_t addr) {
    asm volatile("ldmatrix.sync.aligned.m8n8.x4.shared.b16 {%0,%1,%2,%3}, [%4];"
        : "=r"(r[0]), "=r"(r[1]), "=r"(r[2]), "=r"(r[3]) : "r"(addr));
}

__device__ __forceinline__ void mma16816(float* d, const uint32_t* a, const uint32_t* b) {
    asm volatile("mma.sync.aligned.m16n8k16.row.col.f32.bf16.bf16.f32 "
        "{%0,%1,%2,%3}, {%4,%5,%6,%7}, {%8,%9}, {%0,%1,%2,%3};"
        : "+f"(d[0]), "+f"(d[1]), "+f"(d[2]), "+f"(d[3])
        : "r"(a[0]), "r"(a[1]), "r"(a[2]), "r"(a[3]), "r"(b[0]), "r"(b[1]));
}

__device__ __forceinline__ void split4(float4 v, uint32_t& h0, uint32_t& h1,
                                       uint32_t& l0, uint32_t& l1) {
    __nv_bfloat16 hx = __float2bfloat16(v.x), hy = __float2bfloat16(v.y);
    __nv_bfloat16 hz = __float2bfloat16(v.z), hw = __float2bfloat16(v.w);
    __nv_bfloat16 lx = __float2bfloat16(v.x - __bfloat162float(hx));
    __nv_bfloat16 ly = __float2bfloat16(v.y - __bfloat162float(hy));
    __nv_bfloat16 lz = __float2bfloat16(v.z - __bfloat162float(hz));
    __nv_bfloat16 lw = __float2bfloat16(v.w - __bfloat162float(hw));
    h0 = ((uint32_t)__bfloat16_as_ushort(hy) << 16) | __bfloat16_as_ushort(hx);
    h1 = ((uint32_t)__bfloat16_as_ushort(hw) << 16) | __bfloat16_as_ushort(hz);
    l0 = ((uint32_t)__bfloat16_as_ushort(ly) << 16) | __bfloat16_as_ushort(lx);
    l1 = ((uint32_t)__bfloat16_as_ushort(lw) << 16) | __bfloat16_as_ushort(lz);
}

__device__ __forceinline__ uint32_t sw128(uint32_t off) {
    return off ^ ((off >> 3) & 0x70);
}
__device__ __forceinline__ void st8_sw(char* base, uint32_t byteoff, uint32_t a, uint32_t b) {
    *reinterpret_cast<uint2*>(base + sw128(byteoff)) = make_uint2(a, b);
}

// async copies of pre-converted images into a stage
__device__ __forceinline__ void copyA_async(const uint4* __restrict__ img,
                                            uint32_t sbase, int tid) {
    #pragma unroll
    for (int i = 0; i < 8; i++)
        cpa16(sbase + (uint32_t)(tid + i * 256) * 16u, img + tid + i * 256);
}
__device__ __forceinline__ void copyB_async(const uint4* __restrict__ img,
                                            uint32_t sbase, int tid) {
    #pragma unroll
    for (int i = 0; i < 4; i++)
        cpa16(sbase + 32768u + (uint32_t)(tid + i * 256) * 16u, img + tid + i * 256);
}

__device__ __forceinline__ void mma_tiles(uint32_t sbS, int wm, int wn, uint32_t lane,
                                          float (&acc)[2][4][4]) {
    const int a_r = lane & 15;
    const int a_c = (lane >> 4) * 8;
    const int b_r = (lane & 7) + ((lane >> 4) & 1) * 8;
    const int b_c = ((lane >> 3) & 1) * 8;
    #pragma unroll
    for (int ks = 0; ks < 4; ks++) {
        uint32_t ahi[2][4], alo[2][4], bhi[2][4], blo[2][4];
        #pragma unroll
        for (int o = 0; o < 2; o++) {
            uint32_t off = (uint32_t)(wm * 32 + o * 16 + a_r) * 128
                         + (uint32_t)(ks * 16 + a_c) * 2;
            uint32_t s = sw128(off);
            ldsm4(ahi[o], sbS + A_HI + s);
            ldsm4(alo[o], sbS + A_LO + s);
        }
        #pragma unroll
        for (int g = 0; g < 2; g++) {
            uint32_t off = (uint32_t)(wn * 32 + g * 16 + b_r) * 128
                         + (uint32_t)(ks * 16 + b_c) * 2;
            uint32_t s = sw128(off);
            ldsm4(bhi[g], sbS + B_HI + s);
            ldsm4(blo[g], sbS + B_LO + s);
        }
        #pragma unroll
        for (int o = 0; o < 2; o++)
            #pragma unroll
            for (int j = 0; j < 4; j++) {
                const uint32_t* bh = &bhi[j >> 1][(j & 1) * 2];
                const uint32_t* bl = &blo[j >> 1][(j & 1) * 2];
                mma16816(acc[o][j], ahi[o], bh);
                mma16816(acc[o][j], ahi[o], bl);
                mma16816(acc[o][j], alo[o], bh);
            }
    }
}

__device__ __forceinline__ void stage_D(char* sp, int wm, int wn, uint32_t lane,
                                        float (&acc)[2][4][4]) {
    float* Ds = reinterpret_cast<float*>(sp);
    #pragma unroll
    for (int o = 0; o < 2; o++)
        #pragma unroll
        for (int j = 0; j < 4; j++) {
            int ml = wm * 32 + o * 16 + (int)(lane >> 2);
            int nl = wn * 32 + j * 8 + (int)(lane & 3) * 2;
            *reinterpret_cast<float2*>(&Ds[ml * 68 + nl]) =
                make_float2(acc[o][j][0], acc[o][j][1]);
            *reinterpret_cast<float2*>(&Ds[(ml + 8) * 68 + nl]) =
                make_float2(acc[o][j][2], acc[o][j][3]);
        }
}

#define GEMM_PROLOGUE() \
    extern __shared__ char dsm[]; \
    uint32_t raw = smem_u32(dsm); \
    uint32_t sb = (raw + 1023) & ~1023u; \
    char* sp = dsm + (sb - raw); \
    const int tid = threadIdx.x; \
    const int wid = tid >> 5; \
    const uint32_t lane = tid & 31; \
    const int wm = wid & 3; \
    const int wn = wid >> 2; \
    float acc[2][4][4]; \
    _Pragma("unroll") \
    for (int o = 0; o < 2; o++) \
        _Pragma("unroll") \
        for (int j = 0; j < 4; j++) \
            _Pragma("unroll") \
            for (int e = 0; e < 4; e++) acc[o][j][e] = 0.f;

// ============================================================
// prep: convert X -> A-tile images, 4 weights -> B-tile images
// ============================================================
__global__ __launch_bounds__(256) void prep_kernel(
    const float* __restrict__ X,
    const float* __restrict__ wq, const float* __restrict__ wk,
    const float* __restrict__ wv, const float* __restrict__ wproj)
{
    const int tid = threadIdx.x;
    const int bid = blockIdx.x;
    if (bid < 216) {
        int mt = bid / 12, kt = bid % 12;
        char* img = reinterpret_cast<char*>(g_Xs[bid]);
        #pragma unroll
        for (int i = 0; i < 8; i++) {
            int idx = tid + i * 256;
            int r = idx >> 4, c4 = idx & 15;
            float4 v = *reinterpret_cast<const float4*>(
                &X[(size_t)(mt * 128 + r) * CH + kt * 64 + c4 * 4]);
            uint32_t h0, h1, l0, l1;
            split4(v, h0, h1, l0, l1);
            uint32_t bo = r * 128 + c4 * 8;
            st8_sw(img, bo, h0, h1);
            st8_sw(img + 16384, bo, l0, l1);
        }
    } else {
        int t = bid - 216;
        int w = t / 144; t %= 144;
        const float* Wp = (w == 0) ? wq : (w == 1) ? wk : (w == 2) ? wv : wproj;
        int nt = t / 12, kt = t % 12;
        char* img = reinterpret_cast<char*>(g_Ws[w][t]);
        #pragma unroll
        for (int i = 0; i < 4; i++) {
            int idx = tid + i * 256;
            int r = idx >> 4, c4 = idx & 15;
            float4 v = *reinterpret_cast<const float4*>(
                &Wp[(size_t)(nt * 64 + r) * CH + kt * 64 + c4 * 4]);
            uint32_t h0, h1, l0, l1;
            split4(v, h0, h1, l0, l1);
            uint32_t bo = r * 128 + c4 * 8;
            st8_sw(img, bo, h0, h1);
            st8_sw(img + 8192, bo, l0, l1);
        }
    }
}

// ============================================================
// QKV projection, double-buffered pipeline, z = 0(Q)/1(K)/2(V)
// ============================================================
__global__ __launch_bounds__(256) void qkv_kernel(
    const float* __restrict__ bq,
    const float* __restrict__ bk,
    const float* __restrict__ bv)
{
    GEMM_PROLOGUE();
    const int bx = blockIdx.x;
    const int by = blockIdx.y;
    const int z  = blockIdx.z;
    const int bm = bx * 128;
    const int bn = by * 64;
    const float* bias = (z == 0) ? bq : (z == 1) ? bk : bv;

    copyA_async(g_Xs[bx * 12 + 0], sb, tid);
    copyB_async(g_Ws[z][by * 12 + 0], sb, tid);
    CP_COMMIT();

    for (int c = 0; c < 12; c++) {
        uint32_t cur = sb + (uint32_t)(c & 1) * STAGE;
        if (c < 11) {
            uint32_t nxt = sb + (uint32_t)((c + 1) & 1) * STAGE;
            copyA_async(g_Xs[bx * 12 + c + 1], nxt, tid);
            copyB_async(g_Ws[z][by * 12 + c + 1], nxt, tid);
            CP_COMMIT();
            CP_WAIT1();
        } else {
            CP_WAIT0();
        }
        __syncthreads();
        mma_tiles(cur, wm, wn, lane, acc);
        __syncthreads();
    }
    stage_D(sp, wm, wn, lane, acc);
    __syncthreads();
    float* Ds = reinterpret_cast<float*>(sp);

    if (z == 0) {
        char* img = reinterpret_cast<char*>(g_Qs[by * 18 + bx]);
        #pragma unroll
        for (int i = 0; i < 8; i++) {
            int idx = tid + i * 256;
            int rr = idx >> 4, c4 = idx & 15;
            int n = bn + c4 * 4;
            float* pv = &Ds[rr * 68 + c4 * 4];
            float4 o = make_float4(pv[0] + bias[n], pv[1] + bias[n + 1],
                                   pv[2] + bias[n + 2], pv[3] + bias[n + 3]);
            *reinterpret_cast<float4*>(&g_Q[(size_t)(bm + rr) * CH + n]) = o;
            uint32_t h0, h1, l0, l1;
            split4(o, h0, h1, l0, l1);
            uint32_t bo = rr * 128 + c4 * 8;
            st8_sw(img, bo, h0, h1);
            st8_sw(img + 16384, bo, l0, l1);
        }
    } else if (z == 1) {
        #pragma unroll
        for (int i = 0; i < 8; i++) {
            int idx = tid + i * 256;
            int rr = idx >> 4, c4 = idx & 15;
            int n = bn + c4 * 4;
            float* pv = &Ds[rr * 68 + c4 * 4];
            float4 o = make_float4(pv[0] + bias[n], pv[1] + bias[n + 1],
                                   pv[2] + bias[n + 2], pv[3] + bias[n + 3]);
            char* img = reinterpret_cast<char*>(g_Ks[by * 36 + bx * 2 + (rr >> 6)]);
            uint32_t h0, h1, l0, l1;
            split4(o, h0, h1, l0, l1);
            uint32_t bo = (rr & 63) * 128 + c4 * 8;
            st8_sw(img, bo, h0, h1);
            st8_sw(img + 8192, bo, l0, l1);
        }
    } else {
        #pragma unroll
        for (int i = 0; i < 8; i++) {
            int idx = tid + i * 256;
            int t2 = idx >> 10;
            int rem = idx & 1023;
            int rr = rem >> 4;
            int c4 = rem & 15;
            int tt = t2 * 64 + c4 * 4;
            float b = bias[bn + rr];
            float4 o = make_float4(Ds[(tt + 0) * 68 + rr] + b,
                                   Ds[(tt + 1) * 68 + rr] + b,
                                   Ds[(tt + 2) * 68 + rr] + b,
                                   Ds[(tt + 3) * 68 + rr] + b);
            char* img = reinterpret_cast<char*>(g_Vs[by * 36 + bx * 2 + t2]);
            uint32_t h0, h1, l0, l1;
            split4(o, h0, h1, l0, l1);
            uint32_t bo = rr * 128 + c4 * 8;
            st8_sw(img, bo, h0, h1);
            st8_sw(img + 8192, bo, l0, l1);
        }
    }
}

// ============================================================
// scores (R11 + ky/kx LUT): grid (18, 36, 12), 4 blocks/SM
// ============================================================
__global__ __launch_bounds__(256, 4) void scores2(float* __restrict__ attn)
{
    GEMM_PROLOGUE();
    const int bm = blockIdx.x * 128;
    const int bn = blockIdx.y * 64;
    const int nt = blockIdx.y;
    const int h  = blockIdx.z;
    int2* skyx = reinterpret_cast<int2*>(sp + ROWC);

    copyA_async(g_Qs[h * 18 + blockIdx.x], sb, tid);
    copyB_async(g_Ks[h * 36 + nt], sb, tid);
    CP_COMMIT();
    if (tid < 64) {
        int n = bn + tid;
        skyx[tid] = make_int2(n / SH, n % SH);
    }
    CP_WAIT0();
    __syncthreads();
    mma_tiles(sb, wm, wn, lane, acc);
    __syncthreads();
    stage_D(sp, wm, wn, lane, acc);
    __syncthreads();
    float* Ds = reinterpret_cast<float*>(sp);
    float* Ch = attn + (size_t)h * HW * HW;

    #pragma unroll
    for (int i = 0; i < 8; i++) {
        int idx = tid + i * 256;
        int rr = idx >> 4, c4 = idx & 15;
        int m = bm + rr;
        size_t rb = ((size_t)h * HW + m) * SH;
        float* pv = &Ds[rr * 68 + c4 * 4];
        int2 k0 = skyx[c4 * 4 + 0], k1 = skyx[c4 * 4 + 1];
        int2 k2 = skyx[c4 * 4 + 2], k3 = skyx[c4 * 4 + 3];
        float4 o;
        o.x = QSCALE * pv[0] + g_relh[rb + k0.x] + g_relw[rb + k0.y];
        o.y = QSCALE * pv[1] + g_relh[rb + k1.x] + g_relw[rb + k1.y];
        o.z = QSCALE * pv[2] + g_relh[rb + k2.x] + g_relw[rb + k2.y];
        o.w = QSCALE * pv[3] + g_relh[rb + k3.x] + g_relw[rb + k3.y];
        *reinterpret_cast<float4*>(&Ch[(size_t)m * HW + bn + c4 * 4]) = o;

        float tmax = fmaxf(fmaxf(o.x, o.y), fmaxf(o.z, o.w));
        #pragma unroll
        for (int msk = 1; msk < 16; msk <<= 1)
            tmax = fmaxf(tmax, __shfl_xor_sync(~0u, tmax, msk));
        float tsum = __expf(o.x - tmax) + __expf(o.y - tmax) +
                     __expf(o.z - tmax) + __expf(o.w - tmax);
        #pragma unroll
        for (int msk = 1; msk < 16; msk <<= 1)
            tsum += __shfl_xor_sync(~0u, tsum, msk);
        if (c4 == 0)
            g_part[((size_t)h * HW + m) * NTILES + nt] = make_float2(tmax, tsum);
    }
}

// ============================================================
// combine partials: g_rowC[r] = M + ln(S)
// ============================================================
__global__ __launch_bounds__(256) void combine_kernel()
{
    int r = blockIdx.x * 256 + threadIdx.x;
    const float2* p = &g_part[(size_t)r * NTILES];
    float M = -1e30f;
    #pragma unroll 6
    for (int t = 0; t < NTILES; t++) M = fmaxf(M, p[t].x);
    float S = 0.f;
    #pragma unroll 6
    for (int t = 0; t < NTILES; t++) S += p[t].y * __expf(p[t].x - M);
    g_rowC[r] = M + __logf(S);
}

// ============================================================
// fused softmax + attn.V, split-K, 2-stage pipelined (race-free):
// all writes to stage(c+1) happen AFTER the barrier that proves
// mma(c-1) — the previous reader of that stage — has finished.
// Per iteration: wait B(c) -> barrier -> issue B(c+1), convert
// A(c+1) -> mma(c). convert/mma share no barrier => warp overlap.
// ============================================================
__device__ __forceinline__ void convertA_exp(
    float* __restrict__ Ah, const float* __restrict__ sC,
    int bm, int k0, char* sp, uint32_t stg_off, int tid)
{
    #pragma unroll
    for (int i = 0; i < 8; i++) {
        int idx = tid + i * 256;
        int r = idx >> 4, c4 = idx & 15;
        float* gp = &Ah[(size_t)(bm + r) * HW + k0 + c4 * 4];
        float4 v = *reinterpret_cast<const float4*>(gp);
        float Cv = sC[r];
        v.x = __expf(v.x - Cv); v.y = __expf(v.y - Cv);
        v.z = __expf(v.z - Cv); v.w = __expf(v.w - Cv);
        *reinterpret_cast<float4*>(gp) = v;
        uint32_t h0, h1, l0, l1;
        split4(v, h0, h1, l0, l1);
        uint32_t bo = r * 128 + c4 * 8;
        st8_sw(sp + stg_off + A_HI, bo, h0, h1);
        st8_sw(sp + stg_off + A_LO, bo, l0, l1);
    }
}

__global__ __launch_bounds__(256, 2) void attnv_fused(float* __restrict__ attn)
{
    GEMM_PROLOGUE();
    const int bm = blockIdx.x * 128;
    const int ksg = blockIdx.y;
    const int h  = blockIdx.z;
    float* Ah = attn + (size_t)h * HW * HW;
    float* sC = reinterpret_cast<float*>(sp + 2 * STAGE);

    if (tid < 128) sC[tid] = g_rowC[(size_t)h * HW + bm + tid];
    __syncthreads();

    const int c0 = ksg * (36 / KSPLIT);
    const int c1 = c0 + 36 / KSPLIT;

    // prologue: B(c0) async + A(c0) convert into stage(c0)
    {
        uint32_t s0 = (uint32_t)(c0 & 1) * STAGE;
        copyB_async(g_Vs[h * 36 + c0], sb + s0, tid);
        CP_COMMIT();
        convertA_exp(Ah, sC, bm, c0 * 64, sp, s0, tid);
    }

    for (int c = c0; c < c1; c++) {
        uint32_t cur = sb + (uint32_t)(c & 1) * STAGE;
        CP_WAIT0();               // B(c) landed (only group outstanding)
        __syncthreads();          // A(c) visible; mma(c-1) done -> stage(c+1) free
        if (c + 1 < c1) {
            uint32_t nxtoff = (uint32_t)((c + 1) & 1) * STAGE;
            copyB_async(g_Vs[h * 36 + c + 1], sb + nxtoff, tid);
            CP_COMMIT();
            convertA_exp(Ah, sC, bm, (c + 1) * 64, sp, nxtoff, tid);
        }
        mma_tiles(cur, wm, wn, lane, acc);
    }
    __syncthreads();
    stage_D(sp, wm, wn, lane, acc);
    __syncthreads();
    float* Ds = reinterpret_cast<float*>(sp);
    float* P = g_pOH[ksg];
    #pragma unroll
    for (int i = 0; i < 8; i++) {
        int idx = tid + i * 256;
        int rr = idx >> 4, c4 = idx & 15;
        float* pv = &Ds[rr * 68 + c4 * 4];
        float4 o = make_float4(pv[0], pv[1], pv[2], pv[3]);
        *reinterpret_cast<float4*>(
            &P[(size_t)(bm + rr) * CH + h * 64 + c4 * 4]) = o;
    }
}

// ============================================================
// reduce split-K partials -> OH A-tile images
// ============================================================
__global__ __launch_bounds__(256) void reduce_kernel()
{
    const int tid = threadIdx.x;
    const int mt = blockIdx.x / 12, kt = blockIdx.x % 12;
    char* img = reinterpret_cast<char*>(g_OHs[blockIdx.x]);
    #pragma unroll
    for (int i = 0; i < 8; i++) {
        int idx = tid + i * 256;
        int r = idx >> 4, c4 = idx & 15;
        size_t off = (size_t)(mt * 128 + r) * CH + kt * 64 + c4 * 4;
        float4 a = *reinterpret_cast<const float4*>(&g_pOH[0][off]);
        float4 b = *reinterpret_cast<const float4*>(&g_pOH[1][off]);
        float4 c = *reinterpret_cast<const float4*>(&g_pOH[2][off]);
        float4 d = *reinterpret_cast<const float4*>(&g_pOH[3][off]);
        float4 o = make_float4(a.x + b.x + c.x + d.x, a.y + b.y + c.y + d.y,
                               a.z + b.z + c.z + d.z, a.w + b.w + c.w + d.w);
        uint32_t h0, h1, l0, l1;
        split4(o, h0, h1, l0, l1);
        uint32_t bo = r * 128 + c4 * 8;
        st8_sw(img, bo, h0, h1);
        st8_sw(img + 16384, bo, l0, l1);
    }
}

// ============================================================
// output projection, double-buffered: out = OH @ wproj^T + bproj
// ============================================================
__global__ __launch_bounds__(256) void proj_kernel(
    const float* __restrict__ bias, float* __restrict__ out)
{
    GEMM_PROLOGUE();
    const int bm = blockIdx.x * 128;
    const int bn = blockIdx.y * 64;

    copyA_async(g_OHs[blockIdx.x * 12 + 0], sb, tid);
    copyB_async(g_Ws[3][blockIdx.y * 12 + 0], sb, tid);
    CP_COMMIT();

    for (int c = 0; c < 12; c++) {
        uint32_t cur = sb + (uint32_t)(c & 1) * STAGE;
        if (c < 11) {
            uint32_t nxt = sb + (uint32_t)((c + 1) & 1) * STAGE;
            copyA_async(g_OHs[blockIdx.x * 12 + c + 1], nxt, tid);
            copyB_async(g_Ws[3][blockIdx.y * 12 + c + 1], nxt, tid);
            CP_COMMIT();
            CP_WAIT1();
        } else {
            CP_WAIT0();
        }
        __syncthreads();
        mma_tiles(cur, wm, wn, lane, acc);
        __syncthreads();
    }
    stage_D(sp, wm, wn, lane, acc);
    __syncthreads();
    float* Ds = reinterpret_cast<float*>(sp);
    #pragma unroll
    for (int i = 0; i < 8; i++) {
        int idx = tid + i * 256;
        int rr = idx >> 4, c4 = idx & 15;
        int n = bn + c4 * 4;
        float* pv = &Ds[rr * 68 + c4 * 4];
        float4 o = make_float4(pv[0] + bias[n], pv[1] + bias[n + 1],
                               pv[2] + bias[n + 2], pv[3] + bias[n + 3]);
        *reinterpret_cast<float4*>(&out[(size_t)(bm + rr) * CH + n]) = o;
    }
}

// ============================================================
// rel-pos bias via batched mini-GEMMs (unchanged)
// ============================================================
__global__ __launch_bounds__(256) void relpos2(
    const float* __restrict__ rph, const float* __restrict__ rpw)
{
    const int b   = blockIdx.x;
    const int h   = blockIdx.y;
    const int isW = blockIdx.z;

    __shared__ float Qs[48][68];
    __shared__ float Rs[48][68];

    const int tid = threadIdx.x;
    const float* rtab = isW ? rpw : rph;

    #pragma unroll
    for (int i = 0; i < 3; i++) {
        int idx = tid + i * 256;
        int r = idx >> 4, c4 = idx & 15;
        int m = isW ? (r * SH + b) : (b * SH + r);
        float4 v = *reinterpret_cast<const float4*>(
            &g_Q[(size_t)m * CH + h * HD + c4 * 4]);
        *reinterpret_cast<float4*>(&Qs[r][c4 * 4]) = v;
        float4 w = *reinterpret_cast<const float4*>(
            &rtab[(size_t)(b - r + SH - 1) * HD + c4 * 4]);
        *reinterpret_cast<float4*>(&Rs[r][c4 * 4]) = w;
    }
    __syncthreads();

    const int tx = tid & 15;
    const int ty = tid >> 4;

    float acc[3][3];
    #pragma unroll
    for (int i = 0; i < 3; i++)
        #pragma unroll
        for (int j = 0; j < 3; j++) acc[i][j] = 0.f;

    #pragma unroll 8
    for (int d = 0; d < HD; d++) {
        float a[3], bb[3];
        #pragma unroll
        for (int i = 0; i < 3; i++) a[i] = Qs[tx * 3 + i][d];
        #pragma unroll
        for (int j = 0; j < 3; j++) bb[j] = Rs[ty * 3 + j][d];
        #pragma unroll
        for (int i = 0; i < 3; i++)
            #pragma unroll
            for (int j = 0; j < 3; j++) acc[i][j] += a[i] * bb[j];
    }

    float* out = isW ? g_relw : g_relh;
    #pragma unroll
    for (int i = 0; i < 3; i++) {
        int rr = tx * 3 + i;
        int m = isW ? (rr * SH + b) : (b * SH + rr);
        float* orow = &out[((size_t)h * HW + m) * SH];
        #pragma unroll
        for (int j = 0; j < 3; j++)
            orow[ty * 3 + j] = acc[i][j];
    }
}

// ============================================================
// launch
// ============================================================
extern "C" void kernel_launch(void* const* d_in, const int* in_sizes, int n_in,
                              void* d_out, int out_size)
{
    const float* X     = (const float*)d_in[0];
    const float* wq    = (const float*)d_in[1];
    const float* bq    = (const float*)d_in[2];
    const float* wk    = (const float*)d_in[3];
    const float* bk    = (const float*)d_in[4];
    const float* wv    = (const float*)d_in[5];
    const float* bv    = (const float*)d_in[6];
    const float* wproj = (const float*)d_in[7];
    const float* bproj = (const float*)d_in[8];
    const float* rph   = (const float*)d_in[9];
    const float* rpw   = (const float*)d_in[10];

    float* out_ptr  = (float*)d_out;
    float* attn_ptr = (float*)d_out + OUT_ELEMS;

    cudaFuncSetAttribute(qkv_kernel,  cudaFuncAttributeMaxDynamicSharedMemorySize, SMEM_2S);
    cudaFuncSetAttribute(scores2,     cudaFuncAttributeMaxDynamicSharedMemorySize, SMEM_1S);
    cudaFuncSetAttribute(attnv_fused, cudaFuncAttributeMaxDynamicSharedMemorySize, SMEM_AV);
    cudaFuncSetAttribute(proj_kernel, cudaFuncAttributeMaxDynamicSharedMemorySize, SMEM_2S);

    prep_kernel<<<792, 256>>>(X, wq, wk, wv, wproj);

    qkv_kernel<<<dim3(18, 12, 3), 256, SMEM_2S>>>(bq, bk, bv);

    relpos2<<<dim3(SH, NH, 2), 256>>>(rph, rpw);

    scores2<<<dim3(18, 36, NH), 256, SMEM_1S>>>(attn_ptr);

    combine_kernel<<<108, 256>>>();

    attnv_fused<<<dim3(18, KSPLIT, NH), 256, SMEM_AV>>>(attn_ptr);

    reduce_kernel<<<216, 256>>>();

    proj_kernel<<<dim3(18, 12, 1), 256, SMEM_2S>>>(bproj, out_ptr);
}

// round 14
// speedup vs baseline: 1.1290x; 1.1290x over previous
#include <cuda_runtime.h>
#include <cuda_bf16.h>
#include <cstddef>
#include <cstdint>

#define HW     2304
#define CH     768
#define NH     12
#define HD     64
#define SH     48
#define QSCALE 0.125f
#define OUT_ELEMS (HW * CH)
#define NTILES 36            // 64-col n-tiles per row
#define NT2    72            // 32-col partial tiles per row
#define KSPLIT 4             // attnv split-K segments

// stage layout (49152 B per stage): A_HI 0, A_LO 16384, B_HI 32768, B_LO 40960
#define A_HI  0
#define A_LO  16384
#define B_HI  32768
#define B_LO  40960
#define STAGE 49152
#define ROWC  49152          // attnv row constants (outside stage 0)
#define SMEM_1S (49152 + 512 + 1024)
#define SMEM_2S (2 * 49152 + 1024)

// -------- scratch --------
__device__ uint4  g_Xs [216][2048];      // X A-tiles   (18 mt x 12 kt) 32KB each
__device__ uint4  g_Qs [216][2048];      // Q A-tiles   (12 h  x 18 mt)
__device__ uint4  g_Ks [432][1024];      // K B-tiles   (12 h  x 36 nt) 16KB each
__device__ uint4  g_Vs [432][1024];      // V B-tiles   (12 h  x 36 kt)
__device__ uint4  g_Ws [4][144][1024];   // weight B-tiles (12 nt x 12 kt)
__device__ uint4  g_OHs[216][2048];      // OH A-tiles  (18 mt x 12 kt)

__device__ float  g_Q[HW * CH];              // fp32 Q (relpos input)
__device__ float  g_pOH[KSPLIT][HW * CH];    // attnv split-K partials
__device__ float  g_relh[NH * HW * SH];
__device__ float  g_relw[NH * HW * SH];
__device__ float2 g_part[NH * HW * NT2];     // per (row, 32-col tile): {max, expsum}
__device__ float  g_rowC[NH * HW];           // M + ln(S) per row

// ---------------- helpers ----------------
__device__ __forceinline__ uint32_t smem_u32(const void* p) {
    uint32_t a;
    asm("{ .reg .u64 t; cvta.to.shared.u64 t, %1; cvt.u32.u64 %0, t; }" : "=r"(a) : "l"(p));
    return a;
}

__device__ __forceinline__ void cpa16(uint32_t saddr, const void* g) {
    asm volatile("cp.async.cg.shared.global [%0], [%1], 16;"
        :: "r"(saddr), "l"(g) : "memory");
}
#define CP_COMMIT() asm volatile("cp.async.commit_group;" ::: "memory")
#define CP_WAIT0()  asm volatile("cp.async.wait_group 0;" ::: "memory")
#define CP_WAIT1()  asm volatile("cp.async.wait_group 1;" ::: "memory")

__device__ __forceinline__ void ldsm4(uint32_t* r, uint32_t addr) {
    asm volatile("ldmatrix.sync.aligned.m8n8.x4.shared.b16 {%0,%1,%2,%3}, [%4];"
        : "=r"(r[0]), "=r"(r[1]), "=r"(r[2]), "=r"(r[3]) : "r"(addr));
}

__device__ __forceinline__ void mma16816(float* d, const uint32_t* a, const uint32_t* b) {
    asm volatile("mma.sync.aligned.m16n8k16.row.col.f32.bf16.bf16.f32 "
        "{%0,%1,%2,%3}, {%4,%5,%6,%7}, {%8,%9}, {%0,%1,%2,%3};"
        : "+f"(d[0]), "+f"(d[1]), "+f"(d[2]), "+f"(d[3])
        : "r"(a[0]), "r"(a[1]), "r"(a[2]), "r"(a[3]), "r"(b[0]), "r"(b[1]));
}

__device__ __forceinline__ void split4(float4 v, uint32_t& h0, uint32_t& h1,
                                       uint32_t& l0, uint32_t& l1) {
    __nv_bfloat16 hx = __float2bfloat16(v.x), hy = __float2bfloat16(v.y);
    __nv_bfloat16 hz = __float2bfloat16(v.z), hw = __float2bfloat16(v.w);
    __nv_bfloat16 lx = __float2bfloat16(v.x - __bfloat162float(hx));
    __nv_bfloat16 ly = __float2bfloat16(v.y - __bfloat162float(hy));
    __nv_bfloat16 lz = __float2bfloat16(v.z - __bfloat162float(hz));
    __nv_bfloat16 lw = __float2bfloat16(v.w - __bfloat162float(hw));
    h0 = ((uint32_t)__bfloat16_as_ushort(hy) << 16) | __bfloat16_as_ushort(hx);
    h1 = ((uint32_t)__bfloat16_as_ushort(hw) << 16) | __bfloat16_as_ushort(hz);
    l0 = ((uint32_t)__bfloat16_as_ushort(ly) << 16) | __bfloat16_as_ushort(lx);
    l1 = ((uint32_t)__bfloat16_as_ushort(lw) << 16) | __bfloat16_as_ushort(lz);
}

__device__ __forceinline__ uint32_t sw128(uint32_t off) {
    return off ^ ((off >> 3) & 0x70);
}
__device__ __forceinline__ void st8_sw(char* base, uint32_t byteoff, uint32_t a, uint32_t b) {
    *reinterpret_cast<uint2*>(base + sw128(byteoff)) = make_uint2(a, b);
}

// async copies of pre-converted images into a stage
__device__ __forceinline__ void copyA_async(const uint4* __restrict__ img,
                                            uint32_t sbase, int tid) {
    #pragma unroll
    for (int i = 0; i < 8; i++)
        cpa16(sbase + (uint32_t)(tid + i * 256) * 16u, img + tid + i * 256);
}
__device__ __forceinline__ void copyB_async(const uint4* __restrict__ img,
                                            uint32_t sbase, int tid) {
    #pragma unroll
    for (int i = 0; i < 4; i++)
        cpa16(sbase + 32768u + (uint32_t)(tid + i * 256) * 16u, img + tid + i * 256);
}

__device__ __forceinline__ void mma_tiles(uint32_t sbS, int wm, int wn, uint32_t lane,
                                          float (&acc)[2][4][4]) {
    const int a_r = lane & 15;
    const int a_c = (lane >> 4) * 8;
    const int b_r = (lane & 7) + ((lane >> 4) & 1) * 8;
    const int b_c = ((lane >> 3) & 1) * 8;
    #pragma unroll
    for (int ks = 0; ks < 4; ks++) {
        uint32_t ahi[2][4], alo[2][4], bhi[2][4], blo[2][4];
        #pragma unroll
        for (int o = 0; o < 2; o++) {
            uint32_t off = (uint32_t)(wm * 32 + o * 16 + a_r) * 128
                         + (uint32_t)(ks * 16 + a_c) * 2;
            uint32_t s = sw128(off);
            ldsm4(ahi[o], sbS + A_HI + s);
            ldsm4(alo[o], sbS + A_LO + s);
        }
        #pragma unroll
        for (int g = 0; g < 2; g++) {
            uint32_t off = (uint32_t)(wn * 32 + g * 16 + b_r) * 128
                         + (uint32_t)(ks * 16 + b_c) * 2;
            uint32_t s = sw128(off);
            ldsm4(bhi[g], sbS + B_HI + s);
            ldsm4(blo[g], sbS + B_LO + s);
        }
        #pragma unroll
        for (int o = 0; o < 2; o++)
            #pragma unroll
            for (int j = 0; j < 4; j++) {
                const uint32_t* bh = &bhi[j >> 1][(j & 1) * 2];
                const uint32_t* bl = &blo[j >> 1][(j & 1) * 2];
                mma16816(acc[o][j], ahi[o], bh);
                mma16816(acc[o][j], ahi[o], bl);
                mma16816(acc[o][j], alo[o], bh);
            }
    }
}

__device__ __forceinline__ void stage_D(char* sp, int wm, int wn, uint32_t lane,
                                        float (&acc)[2][4][4]) {
    float* Ds = reinterpret_cast<float*>(sp);
    #pragma unroll
    for (int o = 0; o < 2; o++)
        #pragma unroll
        for (int j = 0; j < 4; j++) {
            int ml = wm * 32 + o * 16 + (int)(lane >> 2);
            int nl = wn * 32 + j * 8 + (int)(lane & 3) * 2;
            *reinterpret_cast<float2*>(&Ds[ml * 68 + nl]) =
                make_float2(acc[o][j][0], acc[o][j][1]);
            *reinterpret_cast<float2*>(&Ds[(ml + 8) * 68 + nl]) =
                make_float2(acc[o][j][2], acc[o][j][3]);
        }
}

#define GEMM_PROLOGUE() \
    extern __shared__ char dsm[]; \
    uint32_t raw = smem_u32(dsm); \
    uint32_t sb = (raw + 1023) & ~1023u; \
    char* sp = dsm + (sb - raw); \
    const int tid = threadIdx.x; \
    const int wid = tid >> 5; \
    const uint32_t lane = tid & 31; \
    const int wm = wid & 3; \
    const int wn = wid >> 2; \
    float acc[2][4][4]; \
    _Pragma("unroll") \
    for (int o = 0; o < 2; o++) \
        _Pragma("unroll") \
        for (int j = 0; j < 4; j++) \
            _Pragma("unroll") \
            for (int e = 0; e < 4; e++) acc[o][j][e] = 0.f;

// ============================================================
// prep: convert X -> A-tile images, 4 weights -> B-tile images
// ============================================================
__global__ __launch_bounds__(256) void prep_kernel(
    const float* __restrict__ X,
    const float* __restrict__ wq, const float* __restrict__ wk,
    const float* __restrict__ wv, const float* __restrict__ wproj)
{
    const int tid = threadIdx.x;
    const int bid = blockIdx.x;
    if (bid < 216) {
        int mt = bid / 12, kt = bid % 12;
        char* img = reinterpret_cast<char*>(g_Xs[bid]);
        #pragma unroll
        for (int i = 0; i < 8; i++) {
            int idx = tid + i * 256;
            int r = idx >> 4, c4 = idx & 15;
            float4 v = *reinterpret_cast<const float4*>(
                &X[(size_t)(mt * 128 + r) * CH + kt * 64 + c4 * 4]);
            uint32_t h0, h1, l0, l1;
            split4(v, h0, h1, l0, l1);
            uint32_t bo = r * 128 + c4 * 8;
            st8_sw(img, bo, h0, h1);
            st8_sw(img + 16384, bo, l0, l1);
        }
    } else {
        int t = bid - 216;
        int w = t / 144; t %= 144;
        const float* Wp = (w == 0) ? wq : (w == 1) ? wk : (w == 2) ? wv : wproj;
        int nt = t / 12, kt = t % 12;
        char* img = reinterpret_cast<char*>(g_Ws[w][t]);
        #pragma unroll
        for (int i = 0; i < 4; i++) {
            int idx = tid + i * 256;
            int r = idx >> 4, c4 = idx & 15;
            float4 v = *reinterpret_cast<const float4*>(
                &Wp[(size_t)(nt * 64 + r) * CH + kt * 64 + c4 * 4]);
            uint32_t h0, h1, l0, l1;
            split4(v, h0, h1, l0, l1);
            uint32_t bo = r * 128 + c4 * 8;
            st8_sw(img, bo, h0, h1);
            st8_sw(img + 8192, bo, l0, l1);
        }
    }
}

// ============================================================
// QKV projection, double-buffered pipeline, z = 0(Q)/1(K)/2(V)
// ============================================================
__global__ __launch_bounds__(256) void qkv_kernel(
    const float* __restrict__ bq,
    const float* __restrict__ bk,
    const float* __restrict__ bv)
{
    GEMM_PROLOGUE();
    const int bx = blockIdx.x;
    const int by = blockIdx.y;
    const int z  = blockIdx.z;
    const int bm = bx * 128;
    const int bn = by * 64;
    const float* bias = (z == 0) ? bq : (z == 1) ? bk : bv;

    copyA_async(g_Xs[bx * 12 + 0], sb, tid);
    copyB_async(g_Ws[z][by * 12 + 0], sb, tid);
    CP_COMMIT();

    for (int c = 0; c < 12; c++) {
        uint32_t cur = sb + (uint32_t)(c & 1) * STAGE;
        if (c < 11) {
            uint32_t nxt = sb + (uint32_t)((c + 1) & 1) * STAGE;
            copyA_async(g_Xs[bx * 12 + c + 1], nxt, tid);
            copyB_async(g_Ws[z][by * 12 + c + 1], nxt, tid);
            CP_COMMIT();
            CP_WAIT1();
        } else {
            CP_WAIT0();
        }
        __syncthreads();
        mma_tiles(cur, wm, wn, lane, acc);
        __syncthreads();
    }
    stage_D(sp, wm, wn, lane, acc);
    __syncthreads();
    float* Ds = reinterpret_cast<float*>(sp);

    if (z == 0) {
        char* img = reinterpret_cast<char*>(g_Qs[by * 18 + bx]);
        #pragma unroll
        for (int i = 0; i < 8; i++) {
            int idx = tid + i * 256;
            int rr = idx >> 4, c4 = idx & 15;
            int n = bn + c4 * 4;
            float* pv = &Ds[rr * 68 + c4 * 4];
            float4 o = make_float4(pv[0] + bias[n], pv[1] + bias[n + 1],
                                   pv[2] + bias[n + 2], pv[3] + bias[n + 3]);
            *reinterpret_cast<float4*>(&g_Q[(size_t)(bm + rr) * CH + n]) = o;
            uint32_t h0, h1, l0, l1;
            split4(o, h0, h1, l0, l1);
            uint32_t bo = rr * 128 + c4 * 8;
            st8_sw(img, bo, h0, h1);
            st8_sw(img + 16384, bo, l0, l1);
        }
    } else if (z == 1) {
        #pragma unroll
        for (int i = 0; i < 8; i++) {
            int idx = tid + i * 256;
            int rr = idx >> 4, c4 = idx & 15;
            int n = bn + c4 * 4;
            float* pv = &Ds[rr * 68 + c4 * 4];
            float4 o = make_float4(pv[0] + bias[n], pv[1] + bias[n + 1],
                                   pv[2] + bias[n + 2], pv[3] + bias[n + 3]);
            char* img = reinterpret_cast<char*>(g_Ks[by * 36 + bx * 2 + (rr >> 6)]);
            uint32_t h0, h1, l0, l1;
            split4(o, h0, h1, l0, l1);
            uint32_t bo = (rr & 63) * 128 + c4 * 8;
            st8_sw(img, bo, h0, h1);
            st8_sw(img + 8192, bo, l0, l1);
        }
    } else {
        #pragma unroll
        for (int i = 0; i < 8; i++) {
            int idx = tid + i * 256;
            int t2 = idx >> 10;
            int rem = idx & 1023;
            int rr = rem >> 4;
            int c4 = rem & 15;
            int tt = t2 * 64 + c4 * 4;
            float b = bias[bn + rr];
            float4 o = make_float4(Ds[(tt + 0) * 68 + rr] + b,
                                   Ds[(tt + 1) * 68 + rr] + b,
                                   Ds[(tt + 2) * 68 + rr] + b,
                                   Ds[(tt + 3) * 68 + rr] + b);
            char* img = reinterpret_cast<char*>(g_Vs[by * 36 + bx * 2 + t2]);
            uint32_t h0, h1, l0, l1;
            split4(o, h0, h1, l0, l1);
            uint32_t bo = rr * 128 + c4 * 8;
            st8_sw(img, bo, h0, h1);
            st8_sw(img + 8192, bo, l0, l1);
        }
    }
}

// ============================================================
// scores (R11 structure; shfl-free softmax partials from smem):
// grid (18, 36, 12), 4 blocks/SM
// ============================================================
__global__ __launch_bounds__(256, 4) void scores2(float* __restrict__ attn)
{
    GEMM_PROLOGUE();
    const int bm = blockIdx.x * 128;
    const int bn = blockIdx.y * 64;
    const int nt = blockIdx.y;
    const int h  = blockIdx.z;

    copyA_async(g_Qs[h * 18 + blockIdx.x], sb, tid);
    copyB_async(g_Ks[h * 36 + nt], sb, tid);
    CP_COMMIT();
    CP_WAIT0();
    __syncthreads();
    mma_tiles(sb, wm, wn, lane, acc);
    __syncthreads();
    stage_D(sp, wm, wn, lane, acc);
    __syncthreads();
    float* Ds = reinterpret_cast<float*>(sp);
    float* Ch = attn + (size_t)h * HW * HW;

    #pragma unroll
    for (int i = 0; i < 8; i++) {
        int idx = tid + i * 256;
        int rr = idx >> 4, c4 = idx & 15;
        int m = bm + rr;
        size_t rb = ((size_t)h * HW + m) * SH;
        int n = bn + c4 * 4;
        float* pv = &Ds[rr * 68 + c4 * 4];
        float4 o;
        o.x = QSCALE * pv[0] + g_relh[rb + (n    ) / SH] + g_relw[rb + (n    ) % SH];
        o.y = QSCALE * pv[1] + g_relh[rb + (n + 1) / SH] + g_relw[rb + (n + 1) % SH];
        o.z = QSCALE * pv[2] + g_relh[rb + (n + 2) / SH] + g_relw[rb + (n + 2) % SH];
        o.w = QSCALE * pv[3] + g_relh[rb + (n + 3) / SH] + g_relw[rb + (n + 3) % SH];
        *reinterpret_cast<float4*>(&Ch[(size_t)m * HW + n]) = o;
        // write final values back into Ds for the partial pass
        *reinterpret_cast<float4*>(pv) = o;
    }
    __syncthreads();

    // shfl-free partials: thread t owns (row = t>>1, half = t&1), 32 cols
    {
        int row = tid >> 1, half = tid & 1;
        const float* pr = &Ds[row * 68 + half * 32];
        float mx = -1e30f;
        #pragma unroll
        for (int j = 0; j < 8; j++) {
            float4 v = *reinterpret_cast<const float4*>(&pr[j * 4]);
            mx = fmaxf(mx, fmaxf(fmaxf(v.x, v.y), fmaxf(v.z, v.w)));
        }
        float sm = 0.f;
        #pragma unroll
        for (int j = 0; j < 8; j++) {
            float4 v = *reinterpret_cast<const float4*>(&pr[j * 4]);
            sm += __expf(v.x - mx) + __expf(v.y - mx)
                + __expf(v.z - mx) + __expf(v.w - mx);
        }
        g_part[((size_t)h * HW + bm + row) * NT2 + nt * 2 + half] =
            make_float2(mx, sm);
    }
}

// ============================================================
// combine partials: g_rowC[r] = M + ln(S)
// ============================================================
__global__ __launch_bounds__(256) void combine_kernel()
{
    int r = blockIdx.x * 256 + threadIdx.x;
    const float2* p = &g_part[(size_t)r * NT2];
    float M = -1e30f;
    #pragma unroll 8
    for (int t = 0; t < NT2; t++) M = fmaxf(M, p[t].x);
    float S = 0.f;
    #pragma unroll 8
    for (int t = 0; t < NT2; t++) S += p[t].y * __expf(p[t].x - M);
    g_rowC[r] = M + __logf(S);
}

// ============================================================
// fused softmax + attn.V, split-K, 3-blocks/SM (R11 version):
// grid (18, KSPLIT, 12). B copy (async) overlaps A exp/split.
// ============================================================
__global__ __launch_bounds__(256, 3) void attnv_fused(float* __restrict__ attn)
{
    GEMM_PROLOGUE();
    const int bm = blockIdx.x * 128;
    const int ksg = blockIdx.y;
    const int h  = blockIdx.z;
    float* Ah = attn + (size_t)h * HW * HW;
    float* sC = reinterpret_cast<float*>(sp + ROWC);

    if (tid < 128) sC[tid] = g_rowC[(size_t)h * HW + bm + tid];
    __syncthreads();

    const int c0 = ksg * (36 / KSPLIT);
    for (int c = c0; c < c0 + 36 / KSPLIT; c++) {
        const int k0 = c * 64;
        copyB_async(g_Vs[h * 36 + c], sb, tid);
        CP_COMMIT();
        #pragma unroll
        for (int i = 0; i < 8; i++) {
            int idx = tid + i * 256;
            int r = idx >> 4, c4 = idx & 15;
            float* gp = &Ah[(size_t)(bm + r) * HW + k0 + c4 * 4];
            float4 v = *reinterpret_cast<const float4*>(gp);
            float Cv = sC[r];
            v.x = __expf(v.x - Cv); v.y = __expf(v.y - Cv);
            v.z = __expf(v.z - Cv); v.w = __expf(v.w - Cv);
            *reinterpret_cast<float4*>(gp) = v;
            uint32_t h0, h1, l0, l1;
            split4(v, h0, h1, l0, l1);
            uint32_t bo = r * 128 + c4 * 8;
            st8_sw(sp + A_HI, bo, h0, h1);
            st8_sw(sp + A_LO, bo, l0, l1);
        }
        CP_WAIT0();
        __syncthreads();
        mma_tiles(sb, wm, wn, lane, acc);
        __syncthreads();
    }
    stage_D(sp, wm, wn, lane, acc);
    __syncthreads();
    float* Ds = reinterpret_cast<float*>(sp);
    float* P = g_pOH[ksg];
    #pragma unroll
    for (int i = 0; i < 8; i++) {
        int idx = tid + i * 256;
        int rr = idx >> 4, c4 = idx & 15;
        float* pv = &Ds[rr * 68 + c4 * 4];
        float4 o = make_float4(pv[0], pv[1], pv[2], pv[3]);
        *reinterpret_cast<float4*>(
            &P[(size_t)(bm + rr) * CH + h * 64 + c4 * 4]) = o;
    }
}

// ============================================================
// reduce split-K partials -> OH A-tile images
// ============================================================
__global__ __launch_bounds__(256) void reduce_kernel()
{
    const int tid = threadIdx.x;
    const int mt = blockIdx.x / 12, kt = blockIdx.x % 12;
    char* img = reinterpret_cast<char*>(g_OHs[blockIdx.x]);
    #pragma unroll
    for (int i = 0; i < 8; i++) {
        int idx = tid + i * 256;
        int r = idx >> 4, c4 = idx & 15;
        size_t off = (size_t)(mt * 128 + r) * CH + kt * 64 + c4 * 4;
        float4 a = *reinterpret_cast<const float4*>(&g_pOH[0][off]);
        float4 b = *reinterpret_cast<const float4*>(&g_pOH[1][off]);
        float4 c = *reinterpret_cast<const float4*>(&g_pOH[2][off]);
        float4 d = *reinterpret_cast<const float4*>(&g_pOH[3][off]);
        float4 o = make_float4(a.x + b.x + c.x + d.x, a.y + b.y + c.y + d.y,
                               a.z + b.z + c.z + d.z, a.w + b.w + c.w + d.w);
        uint32_t h0, h1, l0, l1;
        split4(o, h0, h1, l0, l1);
        uint32_t bo = r * 128 + c4 * 8;
        st8_sw(img, bo, h0, h1);
        st8_sw(img + 16384, bo, l0, l1);
    }
}

// ============================================================
// output projection, double-buffered: out = OH @ wproj^T + bproj
// ============================================================
__global__ __launch_bounds__(256) void proj_kernel(
    const float* __restrict__ bias, float* __restrict__ out)
{
    GEMM_PROLOGUE();
    const int bm = blockIdx.x * 128;
    const int bn = blockIdx.y * 64;

    copyA_async(g_OHs[blockIdx.x * 12 + 0], sb, tid);
    copyB_async(g_Ws[3][blockIdx.y * 12 + 0], sb, tid);
    CP_COMMIT();

    for (int c = 0; c < 12; c++) {
        uint32_t cur = sb + (uint32_t)(c & 1) * STAGE;
        if (c < 11) {
            uint32_t nxt = sb + (uint32_t)((c + 1) & 1) * STAGE;
            copyA_async(g_OHs[blockIdx.x * 12 + c + 1], nxt, tid);
            copyB_async(g_Ws[3][blockIdx.y * 12 + c + 1], nxt, tid);
            CP_COMMIT();
            CP_WAIT1();
        } else {
            CP_WAIT0();
        }
        __syncthreads();
        mma_tiles(cur, wm, wn, lane, acc);
        __syncthreads();
    }
    stage_D(sp, wm, wn, lane, acc);
    __syncthreads();
    float* Ds = reinterpret_cast<float*>(sp);
    #pragma unroll
    for (int i = 0; i < 8; i++) {
        int idx = tid + i * 256;
        int rr = idx >> 4, c4 = idx & 15;
        int n = bn + c4 * 4;
        float* pv = &Ds[rr * 68 + c4 * 4];
        float4 o = make_float4(pv[0] + bias[n], pv[1] + bias[n + 1],
                               pv[2] + bias[n + 2], pv[3] + bias[n + 3]);
        *reinterpret_cast<float4*>(&out[(size_t)(bm + rr) * CH + n]) = o;
    }
}

// ============================================================
// rel-pos bias via batched mini-GEMMs (unchanged)
// ============================================================
__global__ __launch_bounds__(256) void relpos2(
    const float* __restrict__ rph, const float* __restrict__ rpw)
{
    const int b   = blockIdx.x;
    const int h   = blockIdx.y;
    const int isW = blockIdx.z;

    __shared__ float Qs[48][68];
    __shared__ float Rs[48][68];

    const int tid = threadIdx.x;
    const float* rtab = isW ? rpw : rph;

    #pragma unroll
    for (int i = 0; i < 3; i++) {
        int idx = tid + i * 256;
        int r = idx >> 4, c4 = idx & 15;
        int m = isW ? (r * SH + b) : (b * SH + r);
        float4 v = *reinterpret_cast<const float4*>(
            &g_Q[(size_t)m * CH + h * HD + c4 * 4]);
        *reinterpret_cast<float4*>(&Qs[r][c4 * 4]) = v;
        float4 w = *reinterpret_cast<const float4*>(
            &rtab[(size_t)(b - r + SH - 1) * HD + c4 * 4]);
        *reinterpret_cast<float4*>(&Rs[r][c4 * 4]) = w;
    }
    __syncthreads();

    const int tx = tid & 15;
    const int ty = tid >> 4;

    float acc[3][3];
    #pragma unroll
    for (int i = 0; i < 3; i++)
        #pragma unroll
        for (int j = 0; j < 3; j++) acc[i][j] = 0.f;

    #pragma unroll 8
    for (int d = 0; d < HD; d++) {
        float a[3], bb[3];
        #pragma unroll
        for (int i = 0; i < 3; i++) a[i] = Qs[tx * 3 + i][d];
        #pragma unroll
        for (int j = 0; j < 3; j++) bb[j] = Rs[ty * 3 + j][d];
        #pragma unroll
        for (int i = 0; i < 3; i++)
            #pragma unroll
            for (int j = 0; j < 3; j++) acc[i][j] += a[i] * bb[j];
    }

    float* out = isW ? g_relw : g_relh;
    #pragma unroll
    for (int i = 0; i < 3; i++) {
        int rr = tx * 3 + i;
        int m = isW ? (rr * SH + b) : (b * SH + rr);
        float* orow = &out[((size_t)h * HW + m) * SH];
        #pragma unroll
        for (int j = 0; j < 3; j++)
            orow[ty * 3 + j] = acc[i][j];
    }
}

// ============================================================
// launch
// ============================================================
extern "C" void kernel_launch(void* const* d_in, const int* in_sizes, int n_in,
                              void* d_out, int out_size)
{
    const float* X     = (const float*)d_in[0];
    const float* wq    = (const float*)d_in[1];
    const float* bq    = (const float*)d_in[2];
    const float* wk    = (const float*)d_in[3];
    const float* bk    = (const float*)d_in[4];
    const float* wv    = (const float*)d_in[5];
    const float* bv    = (const float*)d_in[6];
    const float* wproj = (const float*)d_in[7];
    const float* bproj = (const float*)d_in[8];
    const float* rph   = (const float*)d_in[9];
    const float* rpw   = (const float*)d_in[10];

    float* out_ptr  = (float*)d_out;
    float* attn_ptr = (float*)d_out + OUT_ELEMS;

    cudaFuncSetAttribute(qkv_kernel,  cudaFuncAttributeMaxDynamicSharedMemorySize, SMEM_2S);
    cudaFuncSetAttribute(scores2,     cudaFuncAttributeMaxDynamicSharedMemorySize, SMEM_1S);
    cudaFuncSetAttribute(attnv_fused, cudaFuncAttributeMaxDynamicSharedMemorySize, SMEM_1S);
    cudaFuncSetAttribute(proj_kernel, cudaFuncAttributeMaxDynamicSharedMemorySize, SMEM_2S);

    prep_kernel<<<792, 256>>>(X, wq, wk, wv, wproj);

    qkv_kernel<<<dim3(18, 12, 3), 256, SMEM_2S>>>(bq, bk, bv);

    relpos2<<<dim3(SH, NH, 2), 256>>>(rph, rpw);

    scores2<<<dim3(18, 36, NH), 256, SMEM_1S>>>(attn_ptr);

    combine_kernel<<<108, 256>>>();

    attnv_fused<<<dim3(18, KSPLIT, NH), 256, SMEM_1S>>>(attn_ptr);

    reduce_kernel<<<216, 256>>>();

    proj_kernel<<<dim3(18, 12, 1), 256, SMEM_2S>>>(bproj, out_ptr);
}

// round 15
// speedup vs baseline: 1.1532x; 1.0214x over previous
#include <cuda_runtime.h>
#include <cuda_bf16.h>
#include <cstddef>
#include <cstdint>

#define HW     2304
#define CH     768
#define NH     12
#define HD     64
#define SH     48
#define QSCALE 0.125f
#define OUT_ELEMS (HW * CH)
#define NTILES 36            // 64-col n-tiles per row
#define NT2    72            // 32-col partial tiles per row
#define KSPLIT 2             // attnv split-K segments

// stage layout (49152 B per stage): A_HI 0, A_LO 16384, B_HI 32768, B_LO 40960
#define A_HI  0
#define A_LO  16384
#define B_HI  32768
#define B_LO  40960
#define STAGE 49152
#define ROWC  49152          // attnv row constants (outside stage 0)
#define SMEM_1S (49152 + 512 + 1024)
#define SMEM_2S (2 * 49152 + 1024)

// -------- scratch --------
__device__ uint4  g_Xs [216][2048];      // X A-tiles   (18 mt x 12 kt) 32KB each
__device__ uint4  g_Qs [216][2048];      // Q A-tiles   (12 h  x 18 mt)
__device__ uint4  g_Ks [432][1024];      // K B-tiles   (12 h  x 36 nt) 16KB each
__device__ uint4  g_Vs [432][1024];      // V B-tiles   (12 h  x 36 kt)
__device__ uint4  g_Ws [4][144][1024];   // weight B-tiles (12 nt x 12 kt)
__device__ uint4  g_OHs[216][2048];      // OH A-tiles  (18 mt x 12 kt)

__device__ float  g_Q[HW * CH];              // fp32 Q (relpos input)
__device__ float  g_pOH[KSPLIT][HW * CH];    // attnv split-K partials
__device__ float  g_relh[NH * HW * SH];
__device__ float  g_relw[NH * HW * SH];
__device__ float2 g_part[NH * HW * NT2];     // per (row, 32-col tile): {max, expsum}
__device__ float  g_rowC[NH * HW];           // M + ln(S) per row

// ---------------- helpers ----------------
__device__ __forceinline__ uint32_t smem_u32(const void* p) {
    uint32_t a;
    asm("{ .reg .u64 t; cvta.to.shared.u64 t, %1; cvt.u32.u64 %0, t; }" : "=r"(a) : "l"(p));
    return a;
}

__device__ __forceinline__ void cpa16(uint32_t saddr, const void* g) {
    asm volatile("cp.async.cg.shared.global [%0], [%1], 16;"
        :: "r"(saddr), "l"(g) : "memory");
}
#define CP_COMMIT() asm volatile("cp.async.commit_group;" ::: "memory")
#define CP_WAIT0()  asm volatile("cp.async.wait_group 0;" ::: "memory")
#define CP_WAIT1()  asm volatile("cp.async.wait_group 1;" ::: "memory")

__device__ __forceinline__ void ldsm4(uint32_t* r, uint32_t addr) {
    asm volatile("ldmatrix.sync.aligned.m8n8.x4.shared.b16 {%0,%1,%2,%3}, [%4];"
        : "=r"(r[0]), "=r"(r[1]), "=r"(r[2]), "=r"(r[3]) : "r"(addr));
}

__device__ __forceinline__ void mma16816(float* d, const uint32_t* a, const uint32_t* b) {
    asm volatile("mma.sync.aligned.m16n8k16.row.col.f32.bf16.bf16.f32 "
        "{%0,%1,%2,%3}, {%4,%5,%6,%7}, {%8,%9}, {%0,%1,%2,%3};"
        : "+f"(d[0]), "+f"(d[1]), "+f"(d[2]), "+f"(d[3])
        : "r"(a[0]), "r"(a[1]), "r"(a[2]), "r"(a[3]), "r"(b[0]), "r"(b[1]));
}

__device__ __forceinline__ void split4(float4 v, uint32_t& h0, uint32_t& h1,
                                       uint32_t& l0, uint32_t& l1) {
    __nv_bfloat16 hx = __float2bfloat16(v.x), hy = __float2bfloat16(v.y);
    __nv_bfloat16 hz = __float2bfloat16(v.z), hw = __float2bfloat16(v.w);
    __nv_bfloat16 lx = __float2bfloat16(v.x - __bfloat162float(hx));
    __nv_bfloat16 ly = __float2bfloat16(v.y - __bfloat162float(hy));
    __nv_bfloat16 lz = __float2bfloat16(v.z - __bfloat162float(hz));
    __nv_bfloat16 lw = __float2bfloat16(v.w - __bfloat162float(hw));
    h0 = ((uint32_t)__bfloat16_as_ushort(hy) << 16) | __bfloat16_as_ushort(hx);
    h1 = ((uint32_t)__bfloat16_as_ushort(hw) << 16) | __bfloat16_as_ushort(hz);
    l0 = ((uint32_t)__bfloat16_as_ushort(ly) << 16) | __bfloat16_as_ushort(lx);
    l1 = ((uint32_t)__bfloat16_as_ushort(lw) << 16) | __bfloat16_as_ushort(lz);
}

__device__ __forceinline__ uint32_t sw128(uint32_t off) {
    return off ^ ((off >> 3) & 0x70);
}
__device__ __forceinline__ void st8_sw(char* base, uint32_t byteoff, uint32_t a, uint32_t b) {
    *reinterpret_cast<uint2*>(base + sw128(byteoff)) = make_uint2(a, b);
}

// async copies of pre-converted images into a stage
__device__ __forceinline__ void copyA_async(const uint4* __restrict__ img,
                                            uint32_t sbase, int tid) {
    #pragma unroll
    for (int i = 0; i < 8; i++)
        cpa16(sbase + (uint32_t)(tid + i * 256) * 16u, img + tid + i * 256);
}
__device__ __forceinline__ void copyB_async(const uint4* __restrict__ img,
                                            uint32_t sbase, int tid) {
    #pragma unroll
    for (int i = 0; i < 4; i++)
        cpa16(sbase + 32768u + (uint32_t)(tid + i * 256) * 16u, img + tid + i * 256);
}

__device__ __forceinline__ void mma_tiles(uint32_t sbS, int wm, int wn, uint32_t lane,
                                          float (&acc)[2][4][4]) {
    const int a_r = lane & 15;
    const int a_c = (lane >> 4) * 8;
    const int b_r = (lane & 7) + ((lane >> 4) & 1) * 8;
    const int b_c = ((lane >> 3) & 1) * 8;
    #pragma unroll
    for (int ks = 0; ks < 4; ks++) {
        uint32_t ahi[2][4], alo[2][4], bhi[2][4], blo[2][4];
        #pragma unroll
        for (int o = 0; o < 2; o++) {
            uint32_t off = (uint32_t)(wm * 32 + o * 16 + a_r) * 128
                         + (uint32_t)(ks * 16 + a_c) * 2;
            uint32_t s = sw128(off);
            ldsm4(ahi[o], sbS + A_HI + s);
            ldsm4(alo[o], sbS + A_LO + s);
        }
        #pragma unroll
        for (int g = 0; g < 2; g++) {
            uint32_t off = (uint32_t)(wn * 32 + g * 16 + b_r) * 128
                         + (uint32_t)(ks * 16 + b_c) * 2;
            uint32_t s = sw128(off);
            ldsm4(bhi[g], sbS + B_HI + s);
            ldsm4(blo[g], sbS + B_LO + s);
        }
        #pragma unroll
        for (int o = 0; o < 2; o++)
            #pragma unroll
            for (int j = 0; j < 4; j++) {
                const uint32_t* bh = &bhi[j >> 1][(j & 1) * 2];
                const uint32_t* bl = &blo[j >> 1][(j & 1) * 2];
                mma16816(acc[o][j], ahi[o], bh);
                mma16816(acc[o][j], ahi[o], bl);
                mma16816(acc[o][j], alo[o], bh);
            }
    }
}

__device__ __forceinline__ void stage_D(char* sp, int wm, int wn, uint32_t lane,
                                        float (&acc)[2][4][4]) {
    float* Ds = reinterpret_cast<float*>(sp);
    #pragma unroll
    for (int o = 0; o < 2; o++)
        #pragma unroll
        for (int j = 0; j < 4; j++) {
            int ml = wm * 32 + o * 16 + (int)(lane >> 2);
            int nl = wn * 32 + j * 8 + (int)(lane & 3) * 2;
            *reinterpret_cast<float2*>(&Ds[ml * 68 + nl]) =
                make_float2(acc[o][j][0], acc[o][j][1]);
            *reinterpret_cast<float2*>(&Ds[(ml + 8) * 68 + nl]) =
                make_float2(acc[o][j][2], acc[o][j][3]);
        }
}

#define GEMM_PROLOGUE() \
    extern __shared__ char dsm[]; \
    uint32_t raw = smem_u32(dsm); \
    uint32_t sb = (raw + 1023) & ~1023u; \
    char* sp = dsm + (sb - raw); \
    const int tid = threadIdx.x; \
    const int wid = tid >> 5; \
    const uint32_t lane = tid & 31; \
    const int wm = wid & 3; \
    const int wn = wid >> 2; \
    float acc[2][4][4]; \
    _Pragma("unroll") \
    for (int o = 0; o < 2; o++) \
        _Pragma("unroll") \
        for (int j = 0; j < 4; j++) \
            _Pragma("unroll") \
            for (int e = 0; e < 4; e++) acc[o][j][e] = 0.f;

// ============================================================
// prep: convert X -> A-tile images, 4 weights -> B-tile images
// ============================================================
__global__ __launch_bounds__(256) void prep_kernel(
    const float* __restrict__ X,
    const float* __restrict__ wq, const float* __restrict__ wk,
    const float* __restrict__ wv, const float* __restrict__ wproj)
{
    const int tid = threadIdx.x;
    const int bid = blockIdx.x;
    if (bid < 216) {
        int mt = bid / 12, kt = bid % 12;
        char* img = reinterpret_cast<char*>(g_Xs[bid]);
        #pragma unroll
        for (int i = 0; i < 8; i++) {
            int idx = tid + i * 256;
            int r = idx >> 4, c4 = idx & 15;
            float4 v = *reinterpret_cast<const float4*>(
                &X[(size_t)(mt * 128 + r) * CH + kt * 64 + c4 * 4]);
            uint32_t h0, h1, l0, l1;
            split4(v, h0, h1, l0, l1);
            uint32_t bo = r * 128 + c4 * 8;
            st8_sw(img, bo, h0, h1);
            st8_sw(img + 16384, bo, l0, l1);
        }
    } else {
        int t = bid - 216;
        int w = t / 144; t %= 144;
        const float* Wp = (w == 0) ? wq : (w == 1) ? wk : (w == 2) ? wv : wproj;
        int nt = t / 12, kt = t % 12;
        char* img = reinterpret_cast<char*>(g_Ws[w][t]);
        #pragma unroll
        for (int i = 0; i < 4; i++) {
            int idx = tid + i * 256;
            int r = idx >> 4, c4 = idx & 15;
            float4 v = *reinterpret_cast<const float4*>(
                &Wp[(size_t)(nt * 64 + r) * CH + kt * 64 + c4 * 4]);
            uint32_t h0, h1, l0, l1;
            split4(v, h0, h1, l0, l1);
            uint32_t bo = r * 128 + c4 * 8;
            st8_sw(img, bo, h0, h1);
            st8_sw(img + 8192, bo, l0, l1);
        }
    }
}

// ============================================================
// QKV projection, double-buffered pipeline, z = 0(Q)/1(K)/2(V)
// ============================================================
__global__ __launch_bounds__(256) void qkv_kernel(
    const float* __restrict__ bq,
    const float* __restrict__ bk,
    const float* __restrict__ bv)
{
    GEMM_PROLOGUE();
    const int bx = blockIdx.x;
    const int by = blockIdx.y;
    const int z  = blockIdx.z;
    const int bm = bx * 128;
    const int bn = by * 64;
    const float* bias = (z == 0) ? bq : (z == 1) ? bk : bv;

    copyA_async(g_Xs[bx * 12 + 0], sb, tid);
    copyB_async(g_Ws[z][by * 12 + 0], sb, tid);
    CP_COMMIT();

    for (int c = 0; c < 12; c++) {
        uint32_t cur = sb + (uint32_t)(c & 1) * STAGE;
        if (c < 11) {
            uint32_t nxt = sb + (uint32_t)((c + 1) & 1) * STAGE;
            copyA_async(g_Xs[bx * 12 + c + 1], nxt, tid);
            copyB_async(g_Ws[z][by * 12 + c + 1], nxt, tid);
            CP_COMMIT();
            CP_WAIT1();
        } else {
            CP_WAIT0();
        }
        __syncthreads();
        mma_tiles(cur, wm, wn, lane, acc);
        __syncthreads();
    }
    stage_D(sp, wm, wn, lane, acc);
    __syncthreads();
    float* Ds = reinterpret_cast<float*>(sp);

    if (z == 0) {
        char* img = reinterpret_cast<char*>(g_Qs[by * 18 + bx]);
        #pragma unroll
        for (int i = 0; i < 8; i++) {
            int idx = tid + i * 256;
            int rr = idx >> 4, c4 = idx & 15;
            int n = bn + c4 * 4;
            float* pv = &Ds[rr * 68 + c4 * 4];
            float4 o = make_float4(pv[0] + bias[n], pv[1] + bias[n + 1],
                                   pv[2] + bias[n + 2], pv[3] + bias[n + 3]);
            *reinterpret_cast<float4*>(&g_Q[(size_t)(bm + rr) * CH + n]) = o;
            uint32_t h0, h1, l0, l1;
            split4(o, h0, h1, l0, l1);
            uint32_t bo = rr * 128 + c4 * 8;
            st8_sw(img, bo, h0, h1);
            st8_sw(img + 16384, bo, l0, l1);
        }
    } else if (z == 1) {
        #pragma unroll
        for (int i = 0; i < 8; i++) {
            int idx = tid + i * 256;
            int rr = idx >> 4, c4 = idx & 15;
            int n = bn + c4 * 4;
            float* pv = &Ds[rr * 68 + c4 * 4];
            float4 o = make_float4(pv[0] + bias[n], pv[1] + bias[n + 1],
                                   pv[2] + bias[n + 2], pv[3] + bias[n + 3]);
            char* img = reinterpret_cast<char*>(g_Ks[by * 36 + bx * 2 + (rr >> 6)]);
            uint32_t h0, h1, l0, l1;
            split4(o, h0, h1, l0, l1);
            uint32_t bo = (rr & 63) * 128 + c4 * 8;
            st8_sw(img, bo, h0, h1);
            st8_sw(img + 8192, bo, l0, l1);
        }
    } else {
        #pragma unroll
        for (int i = 0; i < 8; i++) {
            int idx = tid + i * 256;
            int t2 = idx >> 10;
            int rem = idx & 1023;
            int rr = rem >> 4;
            int c4 = rem & 15;
            int tt = t2 * 64 + c4 * 4;
            float b = bias[bn + rr];
            float4 o = make_float4(Ds[(tt + 0) * 68 + rr] + b,
                                   Ds[(tt + 1) * 68 + rr] + b,
                                   Ds[(tt + 2) * 68 + rr] + b,
                                   Ds[(tt + 3) * 68 + rr] + b);
            char* img = reinterpret_cast<char*>(g_Vs[by * 36 + bx * 2 + t2]);
            uint32_t h0, h1, l0, l1;
            split4(o, h0, h1, l0, l1);
            uint32_t bo = rr * 128 + c4 * 8;
            st8_sw(img, bo, h0, h1);
            st8_sw(img + 8192, bo, l0, l1);
        }
    }
}

// ============================================================
// scores: shfl-free single-pass softmax partials from registers
// grid (18, 36, 12), 4 blocks/SM
// ============================================================
__global__ __launch_bounds__(256, 4) void scores2(float* __restrict__ attn)
{
    GEMM_PROLOGUE();
    const int bm = blockIdx.x * 128;
    const int bn = blockIdx.y * 64;
    const int nt = blockIdx.y;
    const int h  = blockIdx.z;

    copyA_async(g_Qs[h * 18 + blockIdx.x], sb, tid);
    copyB_async(g_Ks[h * 36 + nt], sb, tid);
    CP_COMMIT();
    CP_WAIT0();
    __syncthreads();
    mma_tiles(sb, wm, wn, lane, acc);
    __syncthreads();
    stage_D(sp, wm, wn, lane, acc);
    __syncthreads();
    float* Ds = reinterpret_cast<float*>(sp);
    float* Ch = attn + (size_t)h * HW * HW;

    #pragma unroll
    for (int i = 0; i < 8; i++) {
        int idx = tid + i * 256;
        int rr = idx >> 4, c4 = idx & 15;
        int m = bm + rr;
        size_t rb = ((size_t)h * HW + m) * SH;
        int n = bn + c4 * 4;
        float* pv = &Ds[rr * 68 + c4 * 4];
        float4 o;
        o.x = QSCALE * pv[0] + g_relh[rb + (n    ) / SH] + g_relw[rb + (n    ) % SH];
        o.y = QSCALE * pv[1] + g_relh[rb + (n + 1) / SH] + g_relw[rb + (n + 1) % SH];
        o.z = QSCALE * pv[2] + g_relh[rb + (n + 2) / SH] + g_relw[rb + (n + 2) % SH];
        o.w = QSCALE * pv[3] + g_relh[rb + (n + 3) / SH] + g_relw[rb + (n + 3) % SH];
        *reinterpret_cast<float4*>(&Ch[(size_t)m * HW + n]) = o;
        // write final values back into Ds for the partial pass
        *reinterpret_cast<float4*>(pv) = o;
    }
    __syncthreads();

    // single-pass partials from registers: thread t owns (row=t>>1, half=t&1)
    {
        int row = tid >> 1, half = tid & 1;
        const float* pr = &Ds[row * 68 + half * 32];
        float4 v[8];
        #pragma unroll
        for (int j = 0; j < 8; j++)
            v[j] = *reinterpret_cast<const float4*>(&pr[j * 4]);
        float mx = -1e30f;
        #pragma unroll
        for (int j = 0; j < 8; j++)
            mx = fmaxf(mx, fmaxf(fmaxf(v[j].x, v[j].y), fmaxf(v[j].z, v[j].w)));
        float sm = 0.f;
        #pragma unroll
        for (int j = 0; j < 8; j++)
            sm += __expf(v[j].x - mx) + __expf(v[j].y - mx)
                + __expf(v[j].z - mx) + __expf(v[j].w - mx);
        g_part[((size_t)h * HW + bm + row) * NT2 + nt * 2 + half] =
            make_float2(mx, sm);
    }
}

// ============================================================
// combine partials: g_rowC[r] = M + ln(S)
// ============================================================
__global__ __launch_bounds__(256) void combine_kernel()
{
    int r = blockIdx.x * 256 + threadIdx.x;
    const float2* p = &g_part[(size_t)r * NT2];
    float M = -1e30f;
    #pragma unroll 8
    for (int t = 0; t < NT2; t++) M = fmaxf(M, p[t].x);
    float S = 0.f;
    #pragma unroll 8
    for (int t = 0; t < NT2; t++) S += p[t].y * __expf(p[t].x - M);
    g_rowC[r] = M + __logf(S);
}

// ============================================================
// fused softmax + attn.V, split-K=2, 3-blocks/SM:
// grid (18, KSPLIT, 12) = 432 blocks ≈ one wave.
// ============================================================
__global__ __launch_bounds__(256, 3) void attnv_fused(float* __restrict__ attn)
{
    GEMM_PROLOGUE();
    const int bm = blockIdx.x * 128;
    const int ksg = blockIdx.y;
    const int h  = blockIdx.z;
    float* Ah = attn + (size_t)h * HW * HW;
    float* sC = reinterpret_cast<float*>(sp + ROWC);

    if (tid < 128) sC[tid] = g_rowC[(size_t)h * HW + bm + tid];
    __syncthreads();

    const int c0 = ksg * (36 / KSPLIT);
    for (int c = c0; c < c0 + 36 / KSPLIT; c++) {
        const int k0 = c * 64;
        copyB_async(g_Vs[h * 36 + c], sb, tid);
        CP_COMMIT();
        #pragma unroll
        for (int i = 0; i < 8; i++) {
            int idx = tid + i * 256;
            int r = idx >> 4, c4 = idx & 15;
            float* gp = &Ah[(size_t)(bm + r) * HW + k0 + c4 * 4];
            float4 v = *reinterpret_cast<const float4*>(gp);
            float Cv = sC[r];
            v.x = __expf(v.x - Cv); v.y = __expf(v.y - Cv);
            v.z = __expf(v.z - Cv); v.w = __expf(v.w - Cv);
            *reinterpret_cast<float4*>(gp) = v;
            uint32_t h0, h1, l0, l1;
            split4(v, h0, h1, l0, l1);
            uint32_t bo = r * 128 + c4 * 8;
            st8_sw(sp + A_HI, bo, h0, h1);
            st8_sw(sp + A_LO, bo, l0, l1);
        }
        CP_WAIT0();
        __syncthreads();
        mma_tiles(sb, wm, wn, lane, acc);
        __syncthreads();
    }
    stage_D(sp, wm, wn, lane, acc);
    __syncthreads();
    float* Ds = reinterpret_cast<float*>(sp);
    float* P = g_pOH[ksg];
    #pragma unroll
    for (int i = 0; i < 8; i++) {
        int idx = tid + i * 256;
        int rr = idx >> 4, c4 = idx & 15;
        float* pv = &Ds[rr * 68 + c4 * 4];
        float4 o = make_float4(pv[0], pv[1], pv[2], pv[3]);
        *reinterpret_cast<float4*>(
            &P[(size_t)(bm + rr) * CH + h * 64 + c4 * 4]) = o;
    }
}

// ============================================================
// reduce split-K partials -> OH A-tile images
// ============================================================
__global__ __launch_bounds__(256) void reduce_kernel()
{
    const int tid = threadIdx.x;
    const int mt = blockIdx.x / 12, kt = blockIdx.x % 12;
    char* img = reinterpret_cast<char*>(g_OHs[blockIdx.x]);
    #pragma unroll
    for (int i = 0; i < 8; i++) {
        int idx = tid + i * 256;
        int r = idx >> 4, c4 = idx & 15;
        size_t off = (size_t)(mt * 128 + r) * CH + kt * 64 + c4 * 4;
        float4 a = *reinterpret_cast<const float4*>(&g_pOH[0][off]);
        float4 b = *reinterpret_cast<const float4*>(&g_pOH[1][off]);
        float4 o = make_float4(a.x + b.x, a.y + b.y, a.z + b.z, a.w + b.w);
        uint32_t h0, h1, l0, l1;
        split4(o, h0, h1, l0, l1);
        uint32_t bo = r * 128 + c4 * 8;
        st8_sw(img, bo, h0, h1);
        st8_sw(img + 16384, bo, l0, l1);
    }
}

// ============================================================
// output projection, double-buffered: out = OH @ wproj^T + bproj
// ============================================================
__global__ __launch_bounds__(256) void proj_kernel(
    const float* __restrict__ bias, float* __restrict__ out)
{
    GEMM_PROLOGUE();
    const int bm = blockIdx.x * 128;
    const int bn = blockIdx.y * 64;

    copyA_async(g_OHs[blockIdx.x * 12 + 0], sb, tid);
    copyB_async(g_Ws[3][blockIdx.y * 12 + 0], sb, tid);
    CP_COMMIT();

    for (int c = 0; c < 12; c++) {
        uint32_t cur = sb + (uint32_t)(c & 1) * STAGE;
        if (c < 11) {
            uint32_t nxt = sb + (uint32_t)((c + 1) & 1) * STAGE;
            copyA_async(g_OHs[blockIdx.x * 12 + c + 1], nxt, tid);
            copyB_async(g_Ws[3][blockIdx.y * 12 + c + 1], nxt, tid);
            CP_COMMIT();
            CP_WAIT1();
        } else {
            CP_WAIT0();
        }
        __syncthreads();
        mma_tiles(cur, wm, wn, lane, acc);
        __syncthreads();
    }
    stage_D(sp, wm, wn, lane, acc);
    __syncthreads();
    float* Ds = reinterpret_cast<float*>(sp);
    #pragma unroll
    for (int i = 0; i < 8; i++) {
        int idx = tid + i * 256;
        int rr = idx >> 4, c4 = idx & 15;
        int n = bn + c4 * 4;
        float* pv = &Ds[rr * 68 + c4 * 4];
        float4 o = make_float4(pv[0] + bias[n], pv[1] + bias[n + 1],
                               pv[2] + bias[n + 2], pv[3] + bias[n + 3]);
        *reinterpret_cast<float4*>(&out[(size_t)(bm + rr) * CH + n]) = o;
    }
}

// ============================================================
// rel-pos bias via batched mini-GEMMs (unchanged)
// ============================================================
__global__ __launch_bounds__(256) void relpos2(
    const float* __restrict__ rph, const float* __restrict__ rpw)
{
    const int b   = blockIdx.x;
    const int h   = blockIdx.y;
    const int isW = blockIdx.z;

    __shared__ float Qs[48][68];
    __shared__ float Rs[48][68];

    const int tid = threadIdx.x;
    const float* rtab = isW ? rpw : rph;

    #pragma unroll
    for (int i = 0; i < 3; i++) {
        int idx = tid + i * 256;
        int r = idx >> 4, c4 = idx & 15;
        int m = isW ? (r * SH + b) : (b * SH + r);
        float4 v = *reinterpret_cast<const float4*>(
            &g_Q[(size_t)m * CH + h * HD + c4 * 4]);
        *reinterpret_cast<float4*>(&Qs[r][c4 * 4]) = v;
        float4 w = *reinterpret_cast<const float4*>(
            &rtab[(size_t)(b - r + SH - 1) * HD + c4 * 4]);
        *reinterpret_cast<float4*>(&Rs[r][c4 * 4]) = w;
    }
    __syncthreads();

    const int tx = tid & 15;
    const int ty = tid >> 4;

    float acc[3][3];
    #pragma unroll
    for (int i = 0; i < 3; i++)
        #pragma unroll
        for (int j = 0; j < 3; j++) acc[i][j] = 0.f;

    #pragma unroll 8
    for (int d = 0; d < HD; d++) {
        float a[3], bb[3];
        #pragma unroll
        for (int i = 0; i < 3; i++) a[i] = Qs[tx * 3 + i][d];
        #pragma unroll
        for (int j = 0; j < 3; j++) bb[j] = Rs[ty * 3 + j][d];
        #pragma unroll
        for (int i = 0; i < 3; i++)
            #pragma unroll
            for (int j = 0; j < 3; j++) acc[i][j] += a[i] * bb[j];
    }

    float* out = isW ? g_relw : g_relh;
    #pragma unroll
    for (int i = 0; i < 3; i++) {
        int rr = tx * 3 + i;
        int m = isW ? (rr * SH + b) : (b * SH + rr);
        float* orow = &out[((size_t)h * HW + m) * SH];
        #pragma unroll
        for (int j = 0; j < 3; j++)
            orow[ty * 3 + j] = acc[i][j];
    }
}

// ============================================================
// launch
// ============================================================
extern "C" void kernel_launch(void* const* d_in, const int* in_sizes, int n_in,
                              void* d_out, int out_size)
{
    const float* X     = (const float*)d_in[0];
    const float* wq    = (const float*)d_in[1];
    const float* bq    = (const float*)d_in[2];
    const float* wk    = (const float*)d_in[3];
    const float* bk    = (const float*)d_in[4];
    const float* wv    = (const float*)d_in[5];
    const float* bv    = (const float*)d_in[6];
    const float* wproj = (const float*)d_in[7];
    const float* bproj = (const float*)d_in[8];
    const float* rph   = (const float*)d_in[9];
    const float* rpw   = (const float*)d_in[10];

    float* out_ptr  = (float*)d_out;
    float* attn_ptr = (float*)d_out + OUT_ELEMS;

    cudaFuncSetAttribute(qkv_kernel,  cudaFuncAttributeMaxDynamicSharedMemorySize, SMEM_2S);
    cudaFuncSetAttribute(scores2,     cudaFuncAttributeMaxDynamicSharedMemorySize, SMEM_1S);
    cudaFuncSetAttribute(attnv_fused, cudaFuncAttributeMaxDynamicSharedMemorySize, SMEM_1S);
    cudaFuncSetAttribute(proj_kernel, cudaFuncAttributeMaxDynamicSharedMemorySize, SMEM_2S);

    prep_kernel<<<792, 256>>>(X, wq, wk, wv, wproj);

    qkv_kernel<<<dim3(18, 12, 3), 256, SMEM_2S>>>(bq, bk, bv);

    relpos2<<<dim3(SH, NH, 2), 256>>>(rph, rpw);

    scores2<<<dim3(18, 36, NH), 256, SMEM_1S>>>(attn_ptr);

    combine_kernel<<<108, 256>>>();

    attnv_fused<<<dim3(18, KSPLIT, NH), 256, SMEM_1S>>>(attn_ptr);

    reduce_kernel<<<216, 256>>>();

    proj_kernel<<<dim3(18, 12, 1), 256, SMEM_2S>>>(bproj, out_ptr);
}

// round 16
// speedup vs baseline: 1.1668x; 1.0118x over previous
#include <cuda_runtime.h>
#include <cuda_bf16.h>
#include <cstddef>
#include <cstdint>

#define HW     2304
#define CH     768
#define NH     12
#define HD     64
#define SH     48
#define QSCALE 0.125f
#define OUT_ELEMS (HW * CH)
#define NTILES 36            // 64-col n-tiles per row
#define NT2    72            // 32-col partial tiles per row
#define KSPLIT 2             // attnv split-K segments

// stage layout (49152 B per stage): A_HI 0, A_LO 16384, B_HI 32768, B_LO 40960
#define A_HI  0
#define A_LO  16384
#define B_HI  32768
#define B_LO  40960
#define STAGE 49152
#define ROWC  49152          // attnv row constants (outside stage 0)
#define SMEM_1S (49152 + 512 + 1024)
#define SMEM_2S (2 * 49152 + 1024)

// -------- scratch --------
__device__ uint4  g_Xs [216][2048];      // X A-tiles   (18 mt x 12 kt) 32KB each
__device__ uint4  g_Qs [216][2048];      // Q A-tiles   (12 h  x 18 mt)
__device__ uint4  g_Ks [432][1024];      // K B-tiles   (12 h  x 36 nt) 16KB each
__device__ uint4  g_Vs [432][1024];      // V B-tiles   (12 h  x 36 kt)
__device__ uint4  g_Ws [4][144][1024];   // weight B-tiles (12 nt x 12 kt)
__device__ uint4  g_OHs[216][2048];      // OH A-tiles  (18 mt x 12 kt)

__device__ float  g_Q[HW * CH];              // fp32 Q (relpos input)
__device__ float  g_pOH[KSPLIT][HW * CH];    // attnv split-K partials
__device__ float  g_relh[NH * HW * SH];
__device__ float  g_relw[NH * HW * SH];
__device__ float2 g_part[NH * HW * NT2];     // per (row, 32-col tile): {max, expsum}

// ---------------- helpers ----------------
__device__ __forceinline__ uint32_t smem_u32(const void* p) {
    uint32_t a;
    asm("{ .reg .u64 t; cvta.to.shared.u64 t, %1; cvt.u32.u64 %0, t; }" : "=r"(a) : "l"(p));
    return a;
}

__device__ __forceinline__ void cpa16(uint32_t saddr, const void* g) {
    asm volatile("cp.async.cg.shared.global [%0], [%1], 16;"
        :: "r"(saddr), "l"(g) : "memory");
}
#define CP_COMMIT() asm volatile("cp.async.commit_group;" ::: "memory")
#define CP_WAIT0()  asm volatile("cp.async.wait_group 0;" ::: "memory")
#define CP_WAIT1()  asm volatile("cp.async.wait_group 1;" ::: "memory")

__device__ __forceinline__ void ldsm4(uint32_t* r, uint32_t addr) {
    asm volatile("ldmatrix.sync.aligned.m8n8.x4.shared.b16 {%0,%1,%2,%3}, [%4];"
        : "=r"(r[0]), "=r"(r[1]), "=r"(r[2]), "=r"(r[3]) : "r"(addr));
}

__device__ __forceinline__ void mma16816(float* d, const uint32_t* a, const uint32_t* b) {
    asm volatile("mma.sync.aligned.m16n8k16.row.col.f32.bf16.bf16.f32 "
        "{%0,%1,%2,%3}, {%4,%5,%6,%7}, {%8,%9}, {%0,%1,%2,%3};"
        : "+f"(d[0]), "+f"(d[1]), "+f"(d[2]), "+f"(d[3])
        : "r"(a[0]), "r"(a[1]), "r"(a[2]), "r"(a[3]), "r"(b[0]), "r"(b[1]));
}

__device__ __forceinline__ void split4(float4 v, uint32_t& h0, uint32_t& h1,
                                       uint32_t& l0, uint32_t& l1) {
    __nv_bfloat16 hx = __float2bfloat16(v.x), hy = __float2bfloat16(v.y);
    __nv_bfloat16 hz = __float2bfloat16(v.z), hw = __float2bfloat16(v.w);
    __nv_bfloat16 lx = __float2bfloat16(v.x - __bfloat162float(hx));
    __nv_bfloat16 ly = __float2bfloat16(v.y - __bfloat162float(hy));
    __nv_bfloat16 lz = __float2bfloat16(v.z - __bfloat162float(hz));
    __nv_bfloat16 lw = __float2bfloat16(v.w - __bfloat162float(hw));
    h0 = ((uint32_t)__bfloat16_as_ushort(hy) << 16) | __bfloat16_as_ushort(hx);
    h1 = ((uint32_t)__bfloat16_as_ushort(hw) << 16) | __bfloat16_as_ushort(hz);
    l0 = ((uint32_t)__bfloat16_as_ushort(ly) << 16) | __bfloat16_as_ushort(lx);
    l1 = ((uint32_t)__bfloat16_as_ushort(lw) << 16) | __bfloat16_as_ushort(lz);
}

__device__ __forceinline__ uint32_t sw128(uint32_t off) {
    return off ^ ((off >> 3) & 0x70);
}
__device__ __forceinline__ void st8_sw(char* base, uint32_t byteoff, uint32_t a, uint32_t b) {
    *reinterpret_cast<uint2*>(base + sw128(byteoff)) = make_uint2(a, b);
}

// async copies of pre-converted images into a stage
__device__ __forceinline__ void copyA_async(const uint4* __restrict__ img,
                                            uint32_t sbase, int tid) {
    #pragma unroll
    for (int i = 0; i < 8; i++)
        cpa16(sbase + (uint32_t)(tid + i * 256) * 16u, img + tid + i * 256);
}
__device__ __forceinline__ void copyB_async(const uint4* __restrict__ img,
                                            uint32_t sbase, int tid) {
    #pragma unroll
    for (int i = 0; i < 4; i++)
        cpa16(sbase + 32768u + (uint32_t)(tid + i * 256) * 16u, img + tid + i * 256);
}

__device__ __forceinline__ void mma_tiles(uint32_t sbS, int wm, int wn, uint32_t lane,
                                          float (&acc)[2][4][4]) {
    const int a_r = lane & 15;
    const int a_c = (lane >> 4) * 8;
    const int b_r = (lane & 7) + ((lane >> 4) & 1) * 8;
    const int b_c = ((lane >> 3) & 1) * 8;
    #pragma unroll
    for (int ks = 0; ks < 4; ks++) {
        uint32_t ahi[2][4], alo[2][4], bhi[2][4], blo[2][4];
        #pragma unroll
        for (int o = 0; o < 2; o++) {
            uint32_t off = (uint32_t)(wm * 32 + o * 16 + a_r) * 128
                         + (uint32_t)(ks * 16 + a_c) * 2;
            uint32_t s = sw128(off);
            ldsm4(ahi[o], sbS + A_HI + s);
            ldsm4(alo[o], sbS + A_LO + s);
        }
        #pragma unroll
        for (int g = 0; g < 2; g++) {
            uint32_t off = (uint32_t)(wn * 32 + g * 16 + b_r) * 128
                         + (uint32_t)(ks * 16 + b_c) * 2;
            uint32_t s = sw128(off);
            ldsm4(bhi[g], sbS + B_HI + s);
            ldsm4(blo[g], sbS + B_LO + s);
        }
        #pragma unroll
        for (int o = 0; o < 2; o++)
            #pragma unroll
            for (int j = 0; j < 4; j++) {
                const uint32_t* bh = &bhi[j >> 1][(j & 1) * 2];
                const uint32_t* bl = &blo[j >> 1][(j & 1) * 2];
                mma16816(acc[o][j], ahi[o], bh);
                mma16816(acc[o][j], ahi[o], bl);
                mma16816(acc[o][j], alo[o], bh);
            }
    }
}

__device__ __forceinline__ void stage_D(char* sp, int wm, int wn, uint32_t lane,
                                        float (&acc)[2][4][4]) {
    float* Ds = reinterpret_cast<float*>(sp);
    #pragma unroll
    for (int o = 0; o < 2; o++)
        #pragma unroll
        for (int j = 0; j < 4; j++) {
            int ml = wm * 32 + o * 16 + (int)(lane >> 2);
            int nl = wn * 32 + j * 8 + (int)(lane & 3) * 2;
            *reinterpret_cast<float2*>(&Ds[ml * 68 + nl]) =
                make_float2(acc[o][j][0], acc[o][j][1]);
            *reinterpret_cast<float2*>(&Ds[(ml + 8) * 68 + nl]) =
                make_float2(acc[o][j][2], acc[o][j][3]);
        }
}

#define GEMM_PROLOGUE() \
    extern __shared__ char dsm[]; \
    uint32_t raw = smem_u32(dsm); \
    uint32_t sb = (raw + 1023) & ~1023u; \
    char* sp = dsm + (sb - raw); \
    const int tid = threadIdx.x; \
    const int wid = tid >> 5; \
    const uint32_t lane = tid & 31; \
    const int wm = wid & 3; \
    const int wn = wid >> 2; \
    float acc[2][4][4]; \
    _Pragma("unroll") \
    for (int o = 0; o < 2; o++) \
        _Pragma("unroll") \
        for (int j = 0; j < 4; j++) \
            _Pragma("unroll") \
            for (int e = 0; e < 4; e++) acc[o][j][e] = 0.f;

// ============================================================
// prep: convert X -> A-tile images, 4 weights -> B-tile images
// ============================================================
__global__ __launch_bounds__(256) void prep_kernel(
    const float* __restrict__ X,
    const float* __restrict__ wq, const float* __restrict__ wk,
    const float* __restrict__ wv, const float* __restrict__ wproj)
{
    const int tid = threadIdx.x;
    const int bid = blockIdx.x;
    if (bid < 216) {
        int mt = bid / 12, kt = bid % 12;
        char* img = reinterpret_cast<char*>(g_Xs[bid]);
        #pragma unroll
        for (int i = 0; i < 8; i++) {
            int idx = tid + i * 256;
            int r = idx >> 4, c4 = idx & 15;
            float4 v = *reinterpret_cast<const float4*>(
                &X[(size_t)(mt * 128 + r) * CH + kt * 64 + c4 * 4]);
            uint32_t h0, h1, l0, l1;
            split4(v, h0, h1, l0, l1);
            uint32_t bo = r * 128 + c4 * 8;
            st8_sw(img, bo, h0, h1);
            st8_sw(img + 16384, bo, l0, l1);
        }
    } else {
        int t = bid - 216;
        int w = t / 144; t %= 144;
        const float* Wp = (w == 0) ? wq : (w == 1) ? wk : (w == 2) ? wv : wproj;
        int nt = t / 12, kt = t % 12;
        char* img = reinterpret_cast<char*>(g_Ws[w][t]);
        #pragma unroll
        for (int i = 0; i < 4; i++) {
            int idx = tid + i * 256;
            int r = idx >> 4, c4 = idx & 15;
            float4 v = *reinterpret_cast<const float4*>(
                &Wp[(size_t)(nt * 64 + r) * CH + kt * 64 + c4 * 4]);
            uint32_t h0, h1, l0, l1;
            split4(v, h0, h1, l0, l1);
            uint32_t bo = r * 128 + c4 * 8;
            st8_sw(img, bo, h0, h1);
            st8_sw(img + 8192, bo, l0, l1);
        }
    }
}

// ============================================================
// QKV projection, double-buffered pipeline, z = 0(Q)/1(K)/2(V)
// ============================================================
__global__ __launch_bounds__(256) void qkv_kernel(
    const float* __restrict__ bq,
    const float* __restrict__ bk,
    const float* __restrict__ bv)
{
    GEMM_PROLOGUE();
    const int bx = blockIdx.x;
    const int by = blockIdx.y;
    const int z  = blockIdx.z;
    const int bm = bx * 128;
    const int bn = by * 64;
    const float* bias = (z == 0) ? bq : (z == 1) ? bk : bv;

    copyA_async(g_Xs[bx * 12 + 0], sb, tid);
    copyB_async(g_Ws[z][by * 12 + 0], sb, tid);
    CP_COMMIT();

    for (int c = 0; c < 12; c++) {
        uint32_t cur = sb + (uint32_t)(c & 1) * STAGE;
        if (c < 11) {
            uint32_t nxt = sb + (uint32_t)((c + 1) & 1) * STAGE;
            copyA_async(g_Xs[bx * 12 + c + 1], nxt, tid);
            copyB_async(g_Ws[z][by * 12 + c + 1], nxt, tid);
            CP_COMMIT();
            CP_WAIT1();
        } else {
            CP_WAIT0();
        }
        __syncthreads();
        mma_tiles(cur, wm, wn, lane, acc);
        __syncthreads();
    }
    stage_D(sp, wm, wn, lane, acc);
    __syncthreads();
    float* Ds = reinterpret_cast<float*>(sp);

    if (z == 0) {
        char* img = reinterpret_cast<char*>(g_Qs[by * 18 + bx]);
        #pragma unroll
        for (int i = 0; i < 8; i++) {
            int idx = tid + i * 256;
            int rr = idx >> 4, c4 = idx & 15;
            int n = bn + c4 * 4;
            float* pv = &Ds[rr * 68 + c4 * 4];
            float4 o = make_float4(pv[0] + bias[n], pv[1] + bias[n + 1],
                                   pv[2] + bias[n + 2], pv[3] + bias[n + 3]);
            *reinterpret_cast<float4*>(&g_Q[(size_t)(bm + rr) * CH + n]) = o;
            uint32_t h0, h1, l0, l1;
            split4(o, h0, h1, l0, l1);
            uint32_t bo = rr * 128 + c4 * 8;
            st8_sw(img, bo, h0, h1);
            st8_sw(img + 16384, bo, l0, l1);
        }
    } else if (z == 1) {
        #pragma unroll
        for (int i = 0; i < 8; i++) {
            int idx = tid + i * 256;
            int rr = idx >> 4, c4 = idx & 15;
            int n = bn + c4 * 4;
            float* pv = &Ds[rr * 68 + c4 * 4];
            float4 o = make_float4(pv[0] + bias[n], pv[1] + bias[n + 1],
                                   pv[2] + bias[n + 2], pv[3] + bias[n + 3]);
            char* img = reinterpret_cast<char*>(g_Ks[by * 36 + bx * 2 + (rr >> 6)]);
            uint32_t h0, h1, l0, l1;
            split4(o, h0, h1, l0, l1);
            uint32_t bo = (rr & 63) * 128 + c4 * 8;
            st8_sw(img, bo, h0, h1);
            st8_sw(img + 8192, bo, l0, l1);
        }
    } else {
        #pragma unroll
        for (int i = 0; i < 8; i++) {
            int idx = tid + i * 256;
            int t2 = idx >> 10;
            int rem = idx & 1023;
            int rr = rem >> 4;
            int c4 = rem & 15;
            int tt = t2 * 64 + c4 * 4;
            float b = bias[bn + rr];
            float4 o = make_float4(Ds[(tt + 0) * 68 + rr] + b,
                                   Ds[(tt + 1) * 68 + rr] + b,
                                   Ds[(tt + 2) * 68 + rr] + b,
                                   Ds[(tt + 3) * 68 + rr] + b);
            char* img = reinterpret_cast<char*>(g_Vs[by * 36 + bx * 2 + t2]);
            uint32_t h0, h1, l0, l1;
            split4(o, h0, h1, l0, l1);
            uint32_t bo = rr * 128 + c4 * 8;
            st8_sw(img, bo, h0, h1);
            st8_sw(img + 8192, bo, l0, l1);
        }
    }
}

// ============================================================
// scores: shfl-free single-pass softmax partials from registers
// grid (18, 36, 12), 4 blocks/SM
// ============================================================
__global__ __launch_bounds__(256, 4) void scores2(float* __restrict__ attn)
{
    GEMM_PROLOGUE();
    const int bm = blockIdx.x * 128;
    const int bn = blockIdx.y * 64;
    const int nt = blockIdx.y;
    const int h  = blockIdx.z;

    copyA_async(g_Qs[h * 18 + blockIdx.x], sb, tid);
    copyB_async(g_Ks[h * 36 + nt], sb, tid);
    CP_COMMIT();
    CP_WAIT0();
    __syncthreads();
    mma_tiles(sb, wm, wn, lane, acc);
    __syncthreads();
    stage_D(sp, wm, wn, lane, acc);
    __syncthreads();
    float* Ds = reinterpret_cast<float*>(sp);
    float* Ch = attn + (size_t)h * HW * HW;

    #pragma unroll
    for (int i = 0; i < 8; i++) {
        int idx = tid + i * 256;
        int rr = idx >> 4, c4 = idx & 15;
        int m = bm + rr;
        size_t rb = ((size_t)h * HW + m) * SH;
        int n = bn + c4 * 4;
        float* pv = &Ds[rr * 68 + c4 * 4];
        float4 o;
        o.x = QSCALE * pv[0] + g_relh[rb + (n    ) / SH] + g_relw[rb + (n    ) % SH];
        o.y = QSCALE * pv[1] + g_relh[rb + (n + 1) / SH] + g_relw[rb + (n + 1) % SH];
        o.z = QSCALE * pv[2] + g_relh[rb + (n + 2) / SH] + g_relw[rb + (n + 2) % SH];
        o.w = QSCALE * pv[3] + g_relh[rb + (n + 3) / SH] + g_relw[rb + (n + 3) % SH];
        *reinterpret_cast<float4*>(&Ch[(size_t)m * HW + n]) = o;
        // write final values back into Ds for the partial pass
        *reinterpret_cast<float4*>(pv) = o;
    }
    __syncthreads();

    // single-pass partials from registers: thread t owns (row=t>>1, half=t&1)
    {
        int row = tid >> 1, half = tid & 1;
        const float* pr = &Ds[row * 68 + half * 32];
        float4 v[8];
        #pragma unroll
        for (int j = 0; j < 8; j++)
            v[j] = *reinterpret_cast<const float4*>(&pr[j * 4]);
        float mx = -1e30f;
        #pragma unroll
        for (int j = 0; j < 8; j++)
            mx = fmaxf(mx, fmaxf(fmaxf(v[j].x, v[j].y), fmaxf(v[j].z, v[j].w)));
        float sm = 0.f;
        #pragma unroll
        for (int j = 0; j < 8; j++)
            sm += __expf(v[j].x - mx) + __expf(v[j].y - mx)
                + __expf(v[j].z - mx) + __expf(v[j].w - mx);
        g_part[((size_t)h * HW + bm + row) * NT2 + nt * 2 + half] =
            make_float2(mx, sm);
    }
}

// ============================================================
// fused combine + softmax + attn.V, split-K=2, 3-blocks/SM:
// grid (18, KSPLIT, 12) = 432 blocks ≈ one wave.
// rowC computed inline from g_part (combine kernel eliminated).
// ============================================================
__global__ __launch_bounds__(256, 3) void attnv_fused(float* __restrict__ attn)
{
    GEMM_PROLOGUE();
    const int bm = blockIdx.x * 128;
    const int ksg = blockIdx.y;
    const int h  = blockIdx.z;
    float* Ah = attn + (size_t)h * HW * HW;
    float* sC = reinterpret_cast<float*>(sp + ROWC);

    // inline combine: thread t owns row=t>>1, strided half of 72 partials
    {
        int row = tid >> 1, sub = tid & 1;
        const float2* p = &g_part[((size_t)h * HW + bm + row) * NT2];
        float M = -1e30f;
        #pragma unroll 4
        for (int t = sub; t < NT2; t += 2) M = fmaxf(M, p[t].x);
        float S = 0.f;
        #pragma unroll 4
        for (int t = sub; t < NT2; t += 2) S += p[t].y * __expf(p[t].x - M);
        // merge with pair thread (same warp, lane^1)
        float Mo = __shfl_xor_sync(~0u, M, 1);
        float So = __shfl_xor_sync(~0u, S, 1);
        float Mn = fmaxf(M, Mo);
        float Sn = S * __expf(M - Mn) + So * __expf(Mo - Mn);
        if (sub == 0) sC[row] = Mn + __logf(Sn);
    }
    __syncthreads();

    const int c0 = ksg * (36 / KSPLIT);
    for (int c = c0; c < c0 + 36 / KSPLIT; c++) {
        const int k0 = c * 64;
        copyB_async(g_Vs[h * 36 + c], sb, tid);
        CP_COMMIT();
        #pragma unroll
        for (int i = 0; i < 8; i++) {
            int idx = tid + i * 256;
            int r = idx >> 4, c4 = idx & 15;
            float* gp = &Ah[(size_t)(bm + r) * HW + k0 + c4 * 4];
            float4 v = *reinterpret_cast<const float4*>(gp);
            float Cv = sC[r];
            v.x = __expf(v.x - Cv); v.y = __expf(v.y - Cv);
            v.z = __expf(v.z - Cv); v.w = __expf(v.w - Cv);
            *reinterpret_cast<float4*>(gp) = v;
            uint32_t h0, h1, l0, l1;
            split4(v, h0, h1, l0, l1);
            uint32_t bo = r * 128 + c4 * 8;
            st8_sw(sp + A_HI, bo, h0, h1);
            st8_sw(sp + A_LO, bo, l0, l1);
        }
        CP_WAIT0();
        __syncthreads();
        mma_tiles(sb, wm, wn, lane, acc);
        __syncthreads();
    }
    stage_D(sp, wm, wn, lane, acc);
    __syncthreads();
    float* Ds = reinterpret_cast<float*>(sp);
    float* P = g_pOH[ksg];
    #pragma unroll
    for (int i = 0; i < 8; i++) {
        int idx = tid + i * 256;
        int rr = idx >> 4, c4 = idx & 15;
        float* pv = &Ds[rr * 68 + c4 * 4];
        float4 o = make_float4(pv[0], pv[1], pv[2], pv[3]);
        *reinterpret_cast<float4*>(
            &P[(size_t)(bm + rr) * CH + h * 64 + c4 * 4]) = o;
    }
}

// ============================================================
// reduce split-K partials -> OH A-tile images
// ============================================================
__global__ __launch_bounds__(256) void reduce_kernel()
{
    const int tid = threadIdx.x;
    const int mt = blockIdx.x / 12, kt = blockIdx.x % 12;
    char* img = reinterpret_cast<char*>(g_OHs[blockIdx.x]);
    #pragma unroll
    for (int i = 0; i < 8; i++) {
        int idx = tid + i * 256;
        int r = idx >> 4, c4 = idx & 15;
        size_t off = (size_t)(mt * 128 + r) * CH + kt * 64 + c4 * 4;
        float4 a = *reinterpret_cast<const float4*>(&g_pOH[0][off]);
        float4 b = *reinterpret_cast<const float4*>(&g_pOH[1][off]);
        float4 o = make_float4(a.x + b.x, a.y + b.y, a.z + b.z, a.w + b.w);
        uint32_t h0, h1, l0, l1;
        split4(o, h0, h1, l0, l1);
        uint32_t bo = r * 128 + c4 * 8;
        st8_sw(img, bo, h0, h1);
        st8_sw(img + 16384, bo, l0, l1);
    }
}

// ============================================================
// output projection, double-buffered: out = OH @ wproj^T + bproj
// ============================================================
__global__ __launch_bounds__(256) void proj_kernel(
    const float* __restrict__ bias, float* __restrict__ out)
{
    GEMM_PROLOGUE();
    const int bm = blockIdx.x * 128;
    const int bn = blockIdx.y * 64;

    copyA_async(g_OHs[blockIdx.x * 12 + 0], sb, tid);
    copyB_async(g_Ws[3][blockIdx.y * 12 + 0], sb, tid);
    CP_COMMIT();

    for (int c = 0; c < 12; c++) {
        uint32_t cur = sb + (uint32_t)(c & 1) * STAGE;
        if (c < 11) {
            uint32_t nxt = sb + (uint32_t)((c + 1) & 1) * STAGE;
            copyA_async(g_OHs[blockIdx.x * 12 + c + 1], nxt, tid);
            copyB_async(g_Ws[3][blockIdx.y * 12 + c + 1], nxt, tid);
            CP_COMMIT();
            CP_WAIT1();
        } else {
            CP_WAIT0();
        }
        __syncthreads();
        mma_tiles(cur, wm, wn, lane, acc);
        __syncthreads();
    }
    stage_D(sp, wm, wn, lane, acc);
    __syncthreads();
    float* Ds = reinterpret_cast<float*>(sp);
    #pragma unroll
    for (int i = 0; i < 8; i++) {
        int idx = tid + i * 256;
        int rr = idx >> 4, c4 = idx & 15;
        int n = bn + c4 * 4;
        float* pv = &Ds[rr * 68 + c4 * 4];
        float4 o = make_float4(pv[0] + bias[n], pv[1] + bias[n + 1],
                               pv[2] + bias[n + 2], pv[3] + bias[n + 3]);
        *reinterpret_cast<float4*>(&out[(size_t)(bm + rr) * CH + n]) = o;
    }
}

// ============================================================
// rel-pos bias via batched mini-GEMMs (unchanged)
// ============================================================
__global__ __launch_bounds__(256) void relpos2(
    const float* __restrict__ rph, const float* __restrict__ rpw)
{
    const int b   = blockIdx.x;
    const int h   = blockIdx.y;
    const int isW = blockIdx.z;

    __shared__ float Qs[48][68];
    __shared__ float Rs[48][68];

    const int tid = threadIdx.x;
    const float* rtab = isW ? rpw : rph;

    #pragma unroll
    for (int i = 0; i < 3; i++) {
        int idx = tid + i * 256;
        int r = idx >> 4, c4 = idx & 15;
        int m = isW ? (r * SH + b) : (b * SH + r);
        float4 v = *reinterpret_cast<const float4*>(
            &g_Q[(size_t)m * CH + h * HD + c4 * 4]);
        *reinterpret_cast<float4*>(&Qs[r][c4 * 4]) = v;
        float4 w = *reinterpret_cast<const float4*>(
            &rtab[(size_t)(b - r + SH - 1) * HD + c4 * 4]);
        *reinterpret_cast<float4*>(&Rs[r][c4 * 4]) = w;
    }
    __syncthreads();

    const int tx = tid & 15;
    const int ty = tid >> 4;

    float acc[3][3];
    #pragma unroll
    for (int i = 0; i < 3; i++)
        #pragma unroll
        for (int j = 0; j < 3; j++) acc[i][j] = 0.f;

    #pragma unroll 8
    for (int d = 0; d < HD; d++) {
        float a[3], bb[3];
        #pragma unroll
        for (int i = 0; i < 3; i++) a[i] = Qs[tx * 3 + i][d];
        #pragma unroll
        for (int j = 0; j < 3; j++) bb[j] = Rs[ty * 3 + j][d];
        #pragma unroll
        for (int i = 0; i < 3; i++)
            #pragma unroll
            for (int j = 0; j < 3; j++) acc[i][j] += a[i] * bb[j];
    }

    float* out = isW ? g_relw : g_relh;
    #pragma unroll
    for (int i = 0; i < 3; i++) {
        int rr = tx * 3 + i;
        int m = isW ? (rr * SH + b) : (b * SH + rr);
        float* orow = &out[((size_t)h * HW + m) * SH];
        #pragma unroll
        for (int j = 0; j < 3; j++)
            orow[ty * 3 + j] = acc[i][j];
    }
}

// ============================================================
// launch
// ============================================================
extern "C" void kernel_launch(void* const* d_in, const int* in_sizes, int n_in,
                              void* d_out, int out_size)
{
    const float* X     = (const float*)d_in[0];
    const float* wq    = (const float*)d_in[1];
    const float* bq    = (const float*)d_in[2];
    const float* wk    = (const float*)d_in[3];
    const float* bk    = (const float*)d_in[4];
    const float* wv    = (const float*)d_in[5];
    const float* bv    = (const float*)d_in[6];
    const float* wproj = (const float*)d_in[7];
    const float* bproj = (const float*)d_in[8];
    const float* rph   = (const float*)d_in[9];
    const float* rpw   = (const float*)d_in[10];

    float* out_ptr  = (float*)d_out;
    float* attn_ptr = (float*)d_out + OUT_ELEMS;

    cudaFuncSetAttribute(qkv_kernel,  cudaFuncAttributeMaxDynamicSharedMemorySize, SMEM_2S);
    cudaFuncSetAttribute(scores2,     cudaFuncAttributeMaxDynamicSharedMemorySize, SMEM_1S);
    cudaFuncSetAttribute(attnv_fused, cudaFuncAttributeMaxDynamicSharedMemorySize, SMEM_1S);
    cudaFuncSetAttribute(proj_kernel, cudaFuncAttributeMaxDynamicSharedMemorySize, SMEM_2S);

    prep_kernel<<<792, 256>>>(X, wq, wk, wv, wproj);

    qkv_kernel<<<dim3(18, 12, 3), 256, SMEM_2S>>>(bq, bk, bv);

    relpos2<<<dim3(SH, NH, 2), 256>>>(rph, rpw);

    scores2<<<dim3(18, 36, NH), 256, SMEM_1S>>>(attn_ptr);

    attnv_fused<<<dim3(18, KSPLIT, NH), 256, SMEM_1S>>>(attn_ptr);

    reduce_kernel<<<216, 256>>>();

    proj_kernel<<<dim3(18, 12, 1), 256, SMEM_2S>>>(bproj, out_ptr);
}